// round 2
// baseline (speedup 1.0000x reference)
#include <cuda_runtime.h>
#include <math.h>

#define NMAX 50000
#define EMAX 800000
#define F 256
#define EPS 1e-5f

// ---- device scratch (no allocations allowed) ----
__device__ float  g_h[(size_t)NMAX * F];   // x @ W
__device__ float  g_dinv[NMAX];
__device__ int    g_deg[NMAX];
__device__ int    g_fill[NMAX];
__device__ int    g_ptr[NMAX + 1];
__device__ int    g_csrc[EMAX];
__device__ int    g_partial[256];
__device__ double g_stats[2];              // sum, sumsq
__device__ int    g_is64;                  // edge_index dtype flag

// ------------------------------------------------------------------
// 0a. probe edge_index dtype: int64 storage => first 64 longlongs all in [0,NMAX)
// ------------------------------------------------------------------
__global__ void detect_kernel(const void* __restrict__ ei, int E) {
    if (threadIdx.x == 0 && blockIdx.x == 0) {
        const long long* p = (const long long*)ei;
        int ok = 1;
        int k = (E < 64) ? E : 64;
        for (int i = 0; i < k; i++) {
            long long v = p[i];
            if (v < 0 || v >= NMAX) ok = 0;
        }
        g_is64 = ok;
    }
}

__device__ __forceinline__ int load_idx(const void* ei, size_t pos, int is64) {
    if (is64) return (int)((const long long*)ei)[pos];
    return ((const int*)ei)[pos];
}

// ------------------------------------------------------------------
// 0b. zero scratch
// ------------------------------------------------------------------
__global__ void zero_kernel(int n) {
    int i = blockIdx.x * blockDim.x + threadIdx.x;
    for (; i < n; i += gridDim.x * blockDim.x) {
        g_deg[i] = 0;
        g_fill[i] = 0;
        if (i < 2) g_stats[i] = 0.0;
    }
}

// ------------------------------------------------------------------
// 1. GEMM: H[n,256] = X[n,256] @ W[256,256]   (BM=BN=64, BK=16, 4x4/thread)
// ------------------------------------------------------------------
__global__ __launch_bounds__(256) void gemm_kernel(
    const float* __restrict__ X, const float* __restrict__ W, int n) {
    __shared__ float As[16][68];   // [k][m], padded
    __shared__ float Bs[16][68];   // [k][n], padded

    int tid = threadIdx.x;
    int m0 = blockIdx.y * 64;
    int n0 = blockIdx.x * 64;
    int ty = tid >> 4;             // 0..15 -> row group
    int tx = tid & 15;             // 0..15 -> col group

    float acc[4][4];
#pragma unroll
    for (int i = 0; i < 4; i++)
#pragma unroll
        for (int j = 0; j < 4; j++) acc[i][j] = 0.f;

    for (int k0 = 0; k0 < F; k0 += 16) {
        // load A tile 64x16 (transpose into As[k][m])
        {
            int row = tid >> 2;    // 0..63
            int cg  = tid & 3;     // 0..3 (float4 group)
            int gm = m0 + row;
            float4 v = make_float4(0.f, 0.f, 0.f, 0.f);
            if (gm < n)
                v = *(const float4*)&X[(size_t)gm * F + k0 + cg * 4];
            As[cg * 4 + 0][row] = v.x;
            As[cg * 4 + 1][row] = v.y;
            As[cg * 4 + 2][row] = v.z;
            As[cg * 4 + 3][row] = v.w;
        }
        // load B tile 16x64
        {
            int row = tid >> 4;    // 0..15
            int cg  = tid & 15;    // 0..15
            float4 v = *(const float4*)&W[(size_t)(k0 + row) * F + n0 + cg * 4];
            *(float4*)&Bs[row][cg * 4] = v;
        }
        __syncthreads();
#pragma unroll
        for (int kk = 0; kk < 16; kk++) {
            float4 a = *(float4*)&As[kk][ty * 4];
            float4 b = *(float4*)&Bs[kk][tx * 4];
            acc[0][0] += a.x * b.x; acc[0][1] += a.x * b.y; acc[0][2] += a.x * b.z; acc[0][3] += a.x * b.w;
            acc[1][0] += a.y * b.x; acc[1][1] += a.y * b.y; acc[1][2] += a.y * b.z; acc[1][3] += a.y * b.w;
            acc[2][0] += a.z * b.x; acc[2][1] += a.z * b.y; acc[2][2] += a.z * b.z; acc[2][3] += a.z * b.w;
            acc[3][0] += a.w * b.x; acc[3][1] += a.w * b.y; acc[3][2] += a.w * b.z; acc[3][3] += a.w * b.w;
        }
        __syncthreads();
    }
#pragma unroll
    for (int i = 0; i < 4; i++) {
        int gm = m0 + ty * 4 + i;
        if (gm < n) {
            float4 v = make_float4(acc[i][0], acc[i][1], acc[i][2], acc[i][3]);
            *(float4*)&g_h[(size_t)gm * F + n0 + tx * 4] = v;
        }
    }
}

// ------------------------------------------------------------------
// 2. degree histogram over dst (edges only; self-loop added in dinv)
// ------------------------------------------------------------------
__global__ void deg_kernel(const void* __restrict__ ei, int E, int n) {
    int is64 = g_is64;
    int e = blockIdx.x * blockDim.x + threadIdx.x;
    for (; e < E; e += gridDim.x * blockDim.x) {
        int d = load_idx(ei, (size_t)E + e, is64);
        if ((unsigned)d < (unsigned)n) atomicAdd(&g_deg[d], 1);
    }
}

__global__ void dinv_kernel(int n) {
    int i = blockIdx.x * blockDim.x + threadIdx.x;
    if (i < n) g_dinv[i] = rsqrtf((float)(g_deg[i] + 1));
}

// ------------------------------------------------------------------
// 3. exclusive scan of g_deg -> g_ptr  (3 small kernels)
// ------------------------------------------------------------------
__global__ void scan1_kernel(int n) {   // per-block sums
    int i = blockIdx.x * 512 + threadIdx.x;
    int v = (i < n) ? g_deg[i] : 0;
    for (int o = 16; o > 0; o >>= 1) v += __shfl_down_sync(~0u, v, o);
    __shared__ int wsum[16];
    int lane = threadIdx.x & 31, wid = threadIdx.x >> 5;
    if (lane == 0) wsum[wid] = v;
    __syncthreads();
    if (wid == 0) {
        int s = (lane < 16) ? wsum[lane] : 0;
        for (int o = 8; o > 0; o >>= 1) s += __shfl_down_sync(~0u, s, o);
        if (lane == 0) g_partial[blockIdx.x] = s;
    }
}

__global__ void scan2_kernel(int nb) {  // tiny serial scan of block sums
    if (threadIdx.x == 0 && blockIdx.x == 0) {
        int acc = 0;
        for (int i = 0; i < nb; i++) { int v = g_partial[i]; g_partial[i] = acc; acc += v; }
    }
}

__global__ void scan3_kernel(int n) {   // block-local exclusive scan + offset
    int i = blockIdx.x * 512 + threadIdx.x;
    int v = (i < n) ? g_deg[i] : 0;
    int lane = threadIdx.x & 31, wid = threadIdx.x >> 5;
    int s = v;
    for (int o = 1; o < 32; o <<= 1) {
        int t = __shfl_up_sync(~0u, s, o);
        if (lane >= o) s += t;
    }
    __shared__ int wsum[16];
    if (lane == 31) wsum[wid] = s;
    __syncthreads();
    if (wid == 0) {
        int ws = (lane < 16) ? wsum[lane] : 0;
        for (int o = 1; o < 16; o <<= 1) {
            int t = __shfl_up_sync(~0u, ws, o);
            if (lane >= o) ws += t;
        }
        if (lane < 16) wsum[lane] = ws;
    }
    __syncthreads();
    int excl = s - v + (wid > 0 ? wsum[wid - 1] : 0) + g_partial[blockIdx.x];
    if (i < n)  g_ptr[i] = excl;
    if (i == n - 1) g_ptr[n] = excl + v;
}

// ------------------------------------------------------------------
// 4. fill CSR: for each edge, place src into dst's bucket
// ------------------------------------------------------------------
__global__ void fill_kernel(const void* __restrict__ ei, int E, int n) {
    int is64 = g_is64;
    int e = blockIdx.x * blockDim.x + threadIdx.x;
    for (; e < E; e += gridDim.x * blockDim.x) {
        int s = load_idx(ei, (size_t)e, is64);
        int d = load_idx(ei, (size_t)E + e, is64);
        if ((unsigned)s >= (unsigned)n || (unsigned)d >= (unsigned)n) continue;
        int pos = g_ptr[d] + atomicAdd(&g_fill[d], 1);
        g_csrc[pos] = s;
    }
}

// ------------------------------------------------------------------
// 5. aggregation: one warp per node, gather + register accumulate
//    out[i] = sum_{e: dst=i} h[src]*dinv[src]*dinv[i] + h[i]*dinv[i]^2 + bias
// ------------------------------------------------------------------
__global__ __launch_bounds__(256) void aggregate_kernel(
    const float* __restrict__ bias, float* __restrict__ out, int n) {
    int node = blockIdx.x * 8 + (threadIdx.x >> 5);
    if (node >= n) return;
    int lane = threadIdx.x & 31;

    float di = g_dinv[node];
    const float4* hr = (const float4*)&g_h[(size_t)node * F];
    float w = di * di;
    float4 a0 = hr[lane], a1 = hr[lane + 32];
    float4 acc0 = make_float4(a0.x * w, a0.y * w, a0.z * w, a0.w * w);
    float4 acc1 = make_float4(a1.x * w, a1.y * w, a1.z * w, a1.w * w);

    int beg = g_ptr[node], end = g_ptr[node + 1];
    for (int e = beg; e < end; e++) {
        int s = g_csrc[e];                       // broadcast load
        float nm = g_dinv[s] * di;               // broadcast load
        const float4* hs = (const float4*)&g_h[(size_t)s * F];
        float4 u = hs[lane], v = hs[lane + 32];
        acc0.x += u.x * nm; acc0.y += u.y * nm; acc0.z += u.z * nm; acc0.w += u.w * nm;
        acc1.x += v.x * nm; acc1.y += v.y * nm; acc1.z += v.z * nm; acc1.w += v.w * nm;
    }
    float4 b0 = ((const float4*)bias)[lane];
    float4 b1 = ((const float4*)bias)[lane + 32];
    acc0.x += b0.x; acc0.y += b0.y; acc0.z += b0.z; acc0.w += b0.w;
    acc1.x += b1.x; acc1.y += b1.y; acc1.z += b1.z; acc1.w += b1.w;
    float4* orow = (float4*)&out[(size_t)node * F];
    orow[lane] = acc0;
    orow[lane + 32] = acc1;
}

// ------------------------------------------------------------------
// 6. global sum / sumsq reduction (double accumulation)
// ------------------------------------------------------------------
__global__ void reduce_kernel(const float* __restrict__ out, int M4) {
    double s = 0.0, s2 = 0.0;
    int i = blockIdx.x * blockDim.x + threadIdx.x;
    const float4* o4 = (const float4*)out;
    for (; i < M4; i += gridDim.x * blockDim.x) {
        float4 v = o4[i];
        s  += (double)v.x + (double)v.y + (double)v.z + (double)v.w;
        s2 += (double)v.x * v.x + (double)v.y * v.y + (double)v.z * v.z + (double)v.w * v.w;
    }
    for (int o = 16; o > 0; o >>= 1) {
        s  += __shfl_down_sync(~0u, s, o);
        s2 += __shfl_down_sync(~0u, s2, o);
    }
    __shared__ double sh[2][8];
    int lane = threadIdx.x & 31, wid = threadIdx.x >> 5;
    if (lane == 0) { sh[0][wid] = s; sh[1][wid] = s2; }
    __syncthreads();
    if (wid == 0) {
        double a = (lane < 8) ? sh[0][lane] : 0.0;
        double b = (lane < 8) ? sh[1][lane] : 0.0;
        for (int o = 4; o > 0; o >>= 1) {
            a += __shfl_down_sync(~0u, a, o);
            b += __shfl_down_sync(~0u, b, o);
        }
        if (lane == 0) {
            atomicAdd(&g_stats[0], a);
            atomicAdd(&g_stats[1], b);
        }
    }
}

// ------------------------------------------------------------------
// 7. finalize: layernorm (graph mode) + PReLU, in place
// ------------------------------------------------------------------
__global__ void finalize_kernel(float* __restrict__ out,
                                const float* __restrict__ lnw,
                                const float* __restrict__ lnb,
                                const float* __restrict__ pa, int M) {
    double mu = g_stats[0] / (double)M;
    double var = g_stats[1] / (double)M - mu * mu;
    if (var < 0.0) var = 0.0;
    float inv = 1.f / ((float)sqrt(var) + EPS);
    float fmu = (float)mu;
    float alpha = pa[0];
    int i = blockIdx.x * blockDim.x + threadIdx.x;
    for (; i < M; i += gridDim.x * blockDim.x) {
        int c = i & (F - 1);
        float y = (out[i] - fmu) * inv * lnw[c] + lnb[c];
        out[i] = (y >= 0.f) ? y : alpha * y;
    }
}

// ------------------------------------------------------------------
extern "C" void kernel_launch(void* const* d_in, const int* in_sizes, int n_in,
                              void* d_out, int out_size) {
    const float* x        = (const float*)d_in[0];
    const void*  ei       = d_in[1];               // int32 or int64 (probed)
    // d_in[2] = batch (unused: graph-mode LN ignores it, all zeros)
    const float* W        = (const float*)d_in[3];
    const float* conv_b   = (const float*)d_in[4];
    const float* lnw      = (const float*)d_in[5];
    const float* lnb      = (const float*)d_in[6];
    const float* pa       = (const float*)d_in[7];
    float* out = (float*)d_out;

    int n = in_sizes[0] / F;
    int E = in_sizes[1] / 2;
    int M = n * F;
    int nb = (n + 511) / 512;

    detect_kernel<<<1, 32>>>(ei, E);
    zero_kernel<<<128, 512>>>(n);
    gemm_kernel<<<dim3(F / 64, (n + 63) / 64), 256>>>(x, W, n);
    deg_kernel<<<1024, 256>>>(ei, E, n);
    dinv_kernel<<<(n + 255) / 256, 256>>>(n);
    scan1_kernel<<<nb, 512>>>(n);
    scan2_kernel<<<1, 32>>>(nb);
    scan3_kernel<<<nb, 512>>>(n);
    fill_kernel<<<1024, 256>>>(ei, E, n);
    aggregate_kernel<<<(n + 7) / 8, 256>>>(conv_b, out, n);
    reduce_kernel<<<512, 256>>>(out, M / 4);
    finalize_kernel<<<512, 256>>>(out, lnw, lnb, pa, M);
}

// round 3
// speedup vs baseline: 1.1744x; 1.1744x over previous
#include <cuda_runtime.h>
#include <math.h>

#define NMAX 50000
#define EMAX 800000
#define F 256
#define EPS 1e-5f

#define BM 128
#define BN 128
#define BK 16
#define NT (F / BK)

// ---- device scratch (no allocations allowed) ----
__device__ float  g_h[(size_t)NMAX * F];   // x @ W
__device__ float  g_dinv[NMAX];
__device__ int    g_deg[NMAX];
__device__ int    g_fill[NMAX];
__device__ int    g_ptr[NMAX + 1];
__device__ int    g_csrc[EMAX];
__device__ int    g_partial[256];
__device__ double g_stats[2];              // sum, sumsq
__device__ int    g_is64;                  // edge_index dtype flag

// ------------------------------------------------------------------
// 0a. probe edge_index dtype
// ------------------------------------------------------------------
__global__ void detect_kernel(const void* __restrict__ ei, int E) {
    if (threadIdx.x == 0 && blockIdx.x == 0) {
        const long long* p = (const long long*)ei;
        int ok = 1;
        int k = (E < 64) ? E : 64;
        for (int i = 0; i < k; i++) {
            long long v = p[i];
            if (v < 0 || v >= NMAX) ok = 0;
        }
        g_is64 = ok;
    }
}

__device__ __forceinline__ int load_idx(const void* ei, size_t pos, int is64) {
    if (is64) return (int)((const long long*)ei)[pos];
    return ((const int*)ei)[pos];
}

// ------------------------------------------------------------------
// 0b. zero scratch
// ------------------------------------------------------------------
__global__ void zero_kernel(int n) {
    int i = blockIdx.x * blockDim.x + threadIdx.x;
    for (; i < n; i += gridDim.x * blockDim.x) {
        g_deg[i] = 0;
        g_fill[i] = 0;
        if (i < 2) g_stats[i] = 0.0;
    }
}

// ------------------------------------------------------------------
// 1. GEMM: H[n,256] = X[n,256] @ W[256,256]
//    128x128 tile, BK=16, 8x8 per thread, double-buffered smem
// ------------------------------------------------------------------
__global__ __launch_bounds__(256, 2) void gemm_kernel(
    const float* __restrict__ X, const float* __restrict__ W, int n) {
    __shared__ float As[2][BK][BM + 4];    // [k][m]
    __shared__ float Bs[2][BK][BN + 4];    // [k][n]

    int tid = threadIdx.x;
    int m0 = blockIdx.y * BM;
    int n0 = blockIdx.x * BN;
    int tx = tid & 15;                     // col group 0..15
    int ty = tid >> 4;                     // row group 0..15

    // A-load mapping: 128 rows x 16 cols, 8 floats (2 float4) per thread
    int arow = tid >> 1;                   // 0..127
    int acol = (tid & 1) * 8;              // 0 or 8
    // B-load mapping: 16 rows x 128 cols, 2 float4 per thread
    int brow = tid >> 4;                   // 0..15
    int bcol = (tid & 15) * 4;             // 0..60

    float acc[8][8];
#pragma unroll
    for (int i = 0; i < 8; i++)
#pragma unroll
        for (int j = 0; j < 8; j++) acc[i][j] = 0.f;

    float4 ra0, ra1, rb0, rb1;

    // prologue: load tile 0
    {
        int gm = m0 + arow;
        if (gm < n) {
            ra0 = *(const float4*)&X[(size_t)gm * F + acol];
            ra1 = *(const float4*)&X[(size_t)gm * F + acol + 4];
        } else {
            ra0 = make_float4(0.f, 0.f, 0.f, 0.f); ra1 = ra0;
        }
        rb0 = *(const float4*)&W[(size_t)brow * F + n0 + bcol];
        rb1 = *(const float4*)&W[(size_t)brow * F + n0 + bcol + 64];
        As[0][acol + 0][arow] = ra0.x; As[0][acol + 1][arow] = ra0.y;
        As[0][acol + 2][arow] = ra0.z; As[0][acol + 3][arow] = ra0.w;
        As[0][acol + 4][arow] = ra1.x; As[0][acol + 5][arow] = ra1.y;
        As[0][acol + 6][arow] = ra1.z; As[0][acol + 7][arow] = ra1.w;
        *(float4*)&Bs[0][brow][bcol] = rb0;
        *(float4*)&Bs[0][brow][bcol + 64] = rb1;
    }
    __syncthreads();

#pragma unroll 1
    for (int kt = 0; kt < NT; kt++) {
        int cur = kt & 1;
        int nxt = cur ^ 1;
        // prefetch next tile into registers
        if (kt + 1 < NT) {
            int k0 = (kt + 1) * BK;
            int gm = m0 + arow;
            if (gm < n) {
                ra0 = *(const float4*)&X[(size_t)gm * F + k0 + acol];
                ra1 = *(const float4*)&X[(size_t)gm * F + k0 + acol + 4];
            } else {
                ra0 = make_float4(0.f, 0.f, 0.f, 0.f); ra1 = ra0;
            }
            rb0 = *(const float4*)&W[(size_t)(k0 + brow) * F + n0 + bcol];
            rb1 = *(const float4*)&W[(size_t)(k0 + brow) * F + n0 + bcol + 64];
        }
        // compute current tile
#pragma unroll
        for (int kk = 0; kk < BK; kk++) {
            float4 a0 = *(float4*)&As[cur][kk][ty * 8];
            float4 a1 = *(float4*)&As[cur][kk][ty * 8 + 4];
            float4 b0 = *(float4*)&Bs[cur][kk][tx * 8];
            float4 b1 = *(float4*)&Bs[cur][kk][tx * 8 + 4];
            float af[8] = {a0.x, a0.y, a0.z, a0.w, a1.x, a1.y, a1.z, a1.w};
            float bf[8] = {b0.x, b0.y, b0.z, b0.w, b1.x, b1.y, b1.z, b1.w};
#pragma unroll
            for (int i = 0; i < 8; i++)
#pragma unroll
                for (int j = 0; j < 8; j++)
                    acc[i][j] += af[i] * bf[j];
        }
        // stage next tile into the other buffer
        if (kt + 1 < NT) {
            As[nxt][acol + 0][arow] = ra0.x; As[nxt][acol + 1][arow] = ra0.y;
            As[nxt][acol + 2][arow] = ra0.z; As[nxt][acol + 3][arow] = ra0.w;
            As[nxt][acol + 4][arow] = ra1.x; As[nxt][acol + 5][arow] = ra1.y;
            As[nxt][acol + 6][arow] = ra1.z; As[nxt][acol + 7][arow] = ra1.w;
            *(float4*)&Bs[nxt][brow][bcol] = rb0;
            *(float4*)&Bs[nxt][brow][bcol + 64] = rb1;
        }
        __syncthreads();
    }

#pragma unroll
    for (int i = 0; i < 8; i++) {
        int gm = m0 + ty * 8 + i;
        if (gm < n) {
            float4 v0 = make_float4(acc[i][0], acc[i][1], acc[i][2], acc[i][3]);
            float4 v1 = make_float4(acc[i][4], acc[i][5], acc[i][6], acc[i][7]);
            *(float4*)&g_h[(size_t)gm * F + n0 + tx * 8] = v0;
            *(float4*)&g_h[(size_t)gm * F + n0 + tx * 8 + 4] = v1;
        }
    }
}

// ------------------------------------------------------------------
// 2. degree histogram over dst
// ------------------------------------------------------------------
__global__ void deg_kernel(const void* __restrict__ ei, int E, int n) {
    int is64 = g_is64;
    int e = blockIdx.x * blockDim.x + threadIdx.x;
    for (; e < E; e += gridDim.x * blockDim.x) {
        int d = load_idx(ei, (size_t)E + e, is64);
        if ((unsigned)d < (unsigned)n) atomicAdd(&g_deg[d], 1);
    }
}

__global__ void dinv_kernel(int n) {
    int i = blockIdx.x * blockDim.x + threadIdx.x;
    if (i < n) g_dinv[i] = rsqrtf((float)(g_deg[i] + 1));
}

// ------------------------------------------------------------------
// 3. exclusive scan of g_deg -> g_ptr
// ------------------------------------------------------------------
__global__ void scan1_kernel(int n) {
    int i = blockIdx.x * 512 + threadIdx.x;
    int v = (i < n) ? g_deg[i] : 0;
    for (int o = 16; o > 0; o >>= 1) v += __shfl_down_sync(~0u, v, o);
    __shared__ int wsum[16];
    int lane = threadIdx.x & 31, wid = threadIdx.x >> 5;
    if (lane == 0) wsum[wid] = v;
    __syncthreads();
    if (wid == 0) {
        int s = (lane < 16) ? wsum[lane] : 0;
        for (int o = 8; o > 0; o >>= 1) s += __shfl_down_sync(~0u, s, o);
        if (lane == 0) g_partial[blockIdx.x] = s;
    }
}

__global__ void scan2_kernel(int nb) {
    if (threadIdx.x == 0 && blockIdx.x == 0) {
        int acc = 0;
        for (int i = 0; i < nb; i++) { int v = g_partial[i]; g_partial[i] = acc; acc += v; }
    }
}

__global__ void scan3_kernel(int n) {
    int i = blockIdx.x * 512 + threadIdx.x;
    int v = (i < n) ? g_deg[i] : 0;
    int lane = threadIdx.x & 31, wid = threadIdx.x >> 5;
    int s = v;
    for (int o = 1; o < 32; o <<= 1) {
        int t = __shfl_up_sync(~0u, s, o);
        if (lane >= o) s += t;
    }
    __shared__ int wsum[16];
    if (lane == 31) wsum[wid] = s;
    __syncthreads();
    if (wid == 0) {
        int ws = (lane < 16) ? wsum[lane] : 0;
        for (int o = 1; o < 16; o <<= 1) {
            int t = __shfl_up_sync(~0u, ws, o);
            if (lane >= o) ws += t;
        }
        if (lane < 16) wsum[lane] = ws;
    }
    __syncthreads();
    int excl = s - v + (wid > 0 ? wsum[wid - 1] : 0) + g_partial[blockIdx.x];
    if (i < n)  g_ptr[i] = excl;
    if (i == n - 1) g_ptr[n] = excl + v;
}

// ------------------------------------------------------------------
// 4. fill CSR
// ------------------------------------------------------------------
__global__ void fill_kernel(const void* __restrict__ ei, int E, int n) {
    int is64 = g_is64;
    int e = blockIdx.x * blockDim.x + threadIdx.x;
    for (; e < E; e += gridDim.x * blockDim.x) {
        int s = load_idx(ei, (size_t)e, is64);
        int d = load_idx(ei, (size_t)E + e, is64);
        if ((unsigned)s >= (unsigned)n || (unsigned)d >= (unsigned)n) continue;
        int pos = g_ptr[d] + atomicAdd(&g_fill[d], 1);
        g_csrc[pos] = s;
    }
}

// ------------------------------------------------------------------
// 5. aggregation (warp per node, edge-unrolled x2) + fused LN stats
// ------------------------------------------------------------------
__global__ __launch_bounds__(256) void aggregate_kernel(
    const float* __restrict__ bias, float* __restrict__ out, int n) {
    int wrp = threadIdx.x >> 5;
    int lane = threadIdx.x & 31;
    int node = blockIdx.x * 8 + wrp;
    bool valid = (node < n);

    float4 acc0 = make_float4(0.f, 0.f, 0.f, 0.f);
    float4 acc1 = make_float4(0.f, 0.f, 0.f, 0.f);

    if (valid) {
        float di = g_dinv[node];
        const float4* hr = (const float4*)&g_h[(size_t)node * F];
        float w = di * di;
        float4 a0 = hr[lane], a1 = hr[lane + 32];
        acc0 = make_float4(a0.x * w, a0.y * w, a0.z * w, a0.w * w);
        acc1 = make_float4(a1.x * w, a1.y * w, a1.z * w, a1.w * w);

        int beg = g_ptr[node], end = g_ptr[node + 1];
        int e = beg;
        for (; e + 1 < end; e += 2) {
            int s0 = g_csrc[e];
            int s1 = g_csrc[e + 1];
            float nm0 = g_dinv[s0] * di;
            float nm1 = g_dinv[s1] * di;
            const float4* h0 = (const float4*)&g_h[(size_t)s0 * F];
            const float4* h1 = (const float4*)&g_h[(size_t)s1 * F];
            float4 u0 = h0[lane], v0 = h0[lane + 32];
            float4 u1 = h1[lane], v1 = h1[lane + 32];
            acc0.x += u0.x * nm0; acc0.y += u0.y * nm0; acc0.z += u0.z * nm0; acc0.w += u0.w * nm0;
            acc1.x += v0.x * nm0; acc1.y += v0.y * nm0; acc1.z += v0.z * nm0; acc1.w += v0.w * nm0;
            acc0.x += u1.x * nm1; acc0.y += u1.y * nm1; acc0.z += u1.z * nm1; acc0.w += u1.w * nm1;
            acc1.x += v1.x * nm1; acc1.y += v1.y * nm1; acc1.z += v1.z * nm1; acc1.w += v1.w * nm1;
        }
        if (e < end) {
            int s0 = g_csrc[e];
            float nm0 = g_dinv[s0] * di;
            const float4* h0 = (const float4*)&g_h[(size_t)s0 * F];
            float4 u0 = h0[lane], v0 = h0[lane + 32];
            acc0.x += u0.x * nm0; acc0.y += u0.y * nm0; acc0.z += u0.z * nm0; acc0.w += u0.w * nm0;
            acc1.x += v0.x * nm0; acc1.y += v0.y * nm0; acc1.z += v0.z * nm0; acc1.w += v0.w * nm0;
        }
        float4 b0 = ((const float4*)bias)[lane];
        float4 b1 = ((const float4*)bias)[lane + 32];
        acc0.x += b0.x; acc0.y += b0.y; acc0.z += b0.z; acc0.w += b0.w;
        acc1.x += b1.x; acc1.y += b1.y; acc1.z += b1.z; acc1.w += b1.w;
        float4* orow = (float4*)&out[(size_t)node * F];
        orow[lane] = acc0;
        orow[lane + 32] = acc1;
    }

    // fused LN statistics: block-partial sums -> one double atomic per block
    float s  = acc0.x + acc0.y + acc0.z + acc0.w + acc1.x + acc1.y + acc1.z + acc1.w;
    float s2 = acc0.x * acc0.x + acc0.y * acc0.y + acc0.z * acc0.z + acc0.w * acc0.w
             + acc1.x * acc1.x + acc1.y * acc1.y + acc1.z * acc1.z + acc1.w * acc1.w;
    if (!valid) { s = 0.f; s2 = 0.f; }
    for (int o = 16; o > 0; o >>= 1) {
        s  += __shfl_down_sync(~0u, s, o);
        s2 += __shfl_down_sync(~0u, s2, o);
    }
    __shared__ float sh_s[8], sh_s2[8];
    if (lane == 0) { sh_s[wrp] = s; sh_s2[wrp] = s2; }
    __syncthreads();
    if (threadIdx.x == 0) {
        double a = 0.0, b = 0.0;
        for (int i = 0; i < 8; i++) { a += (double)sh_s[i]; b += (double)sh_s2[i]; }
        atomicAdd(&g_stats[0], a);
        atomicAdd(&g_stats[1], b);
    }
}

// ------------------------------------------------------------------
// 7. finalize: layernorm (graph mode) + PReLU, in place
// ------------------------------------------------------------------
__global__ void finalize_kernel(float* __restrict__ out,
                                const float* __restrict__ lnw,
                                const float* __restrict__ lnb,
                                const float* __restrict__ pa, int M) {
    double mu = g_stats[0] / (double)M;
    double var = g_stats[1] / (double)M - mu * mu;
    if (var < 0.0) var = 0.0;
    float inv = 1.f / ((float)sqrt(var) + EPS);
    float fmu = (float)mu;
    float alpha = pa[0];
    int i = blockIdx.x * blockDim.x + threadIdx.x;
    for (; i < M; i += gridDim.x * blockDim.x) {
        int c = i & (F - 1);
        float y = (out[i] - fmu) * inv * lnw[c] + lnb[c];
        out[i] = (y >= 0.f) ? y : alpha * y;
    }
}

// ------------------------------------------------------------------
extern "C" void kernel_launch(void* const* d_in, const int* in_sizes, int n_in,
                              void* d_out, int out_size) {
    const float* x        = (const float*)d_in[0];
    const void*  ei       = d_in[1];               // int32 or int64 (probed)
    const float* W        = (const float*)d_in[3];
    const float* conv_b   = (const float*)d_in[4];
    const float* lnw      = (const float*)d_in[5];
    const float* lnb      = (const float*)d_in[6];
    const float* pa       = (const float*)d_in[7];
    float* out = (float*)d_out;

    int n = in_sizes[0] / F;
    int E = in_sizes[1] / 2;
    int M = n * F;
    int nb = (n + 511) / 512;

    detect_kernel<<<1, 32>>>(ei, E);
    zero_kernel<<<128, 512>>>(n);
    gemm_kernel<<<dim3(F / BN, (n + BM - 1) / BM), 256>>>(x, W, n);
    deg_kernel<<<1024, 256>>>(ei, E, n);
    dinv_kernel<<<(n + 255) / 256, 256>>>(n);
    scan1_kernel<<<nb, 512>>>(n);
    scan2_kernel<<<1, 32>>>(nb);
    scan3_kernel<<<nb, 512>>>(n);
    fill_kernel<<<1024, 256>>>(ei, E, n);
    aggregate_kernel<<<(n + 7) / 8, 256>>>(conv_b, out, n);
    finalize_kernel<<<512, 256>>>(out, lnw, lnb, pa, M);
}

// round 6
// speedup vs baseline: 1.5123x; 1.2877x over previous
#include <cuda_runtime.h>
#include <cuda_bf16.h>
#include <math.h>
#include <cstdint>

#define NMAX 50000
#define EMAX 800000
#define F 256
#define EPS 1e-5f

// ---- device scratch ----
__device__ float          g_h[(size_t)NMAX * F];
__device__ __nv_bfloat16  g_xh[(size_t)NMAX * F];
__device__ __nv_bfloat16  g_xl[(size_t)NMAX * F];
__device__ __nv_bfloat16  g_wth[F * F];       // W^T high  [n][k]
__device__ __nv_bfloat16  g_wtl[F * F];       // W^T low
__device__ float  g_dinv[NMAX];
__device__ int    g_deg[NMAX];
__device__ int    g_fill[NMAX];
__device__ int    g_ptr[NMAX + 1];
__device__ int    g_csrc[EMAX];
__device__ int    g_partial[256];
__device__ double g_stats[2];
__device__ int    g_is64;

// ------------------------------------------------------------------
// split helpers
// ------------------------------------------------------------------
__device__ __forceinline__ uint32_t pack_bf16(float a, float b) {
    __nv_bfloat162 t;
    t.x = __float2bfloat16_rn(a);
    t.y = __float2bfloat16_rn(b);
    return *(uint32_t*)&t;
}
__device__ __forceinline__ void split8(const float* f, uint4& h, uint4& l) {
    float hv[8], lv[8];
#pragma unroll
    for (int j = 0; j < 8; j++) {
        __nv_bfloat16 b = __float2bfloat16_rn(f[j]);
        hv[j] = __bfloat162float(b);
        lv[j] = f[j] - hv[j];
    }
    h = make_uint4(pack_bf16(hv[0], hv[1]), pack_bf16(hv[2], hv[3]),
                   pack_bf16(hv[4], hv[5]), pack_bf16(hv[6], hv[7]));
    l = make_uint4(pack_bf16(lv[0], lv[1]), pack_bf16(lv[2], lv[3]),
                   pack_bf16(lv[4], lv[5]), pack_bf16(lv[6], lv[7]));
}

// split X -> bf16 high/low
__global__ void split_x_kernel(const float* __restrict__ X, int n8) {
    int i = blockIdx.x * blockDim.x + threadIdx.x;
    for (; i < n8; i += gridDim.x * blockDim.x) {
        float f[8];
        float4 v0 = ((const float4*)X)[i * 2];
        float4 v1 = ((const float4*)X)[i * 2 + 1];
        f[0] = v0.x; f[1] = v0.y; f[2] = v0.z; f[3] = v0.w;
        f[4] = v1.x; f[5] = v1.y; f[6] = v1.z; f[7] = v1.w;
        uint4 h, l;
        split8(f, h, l);
        ((uint4*)g_xh)[i] = h;
        ((uint4*)g_xl)[i] = l;
    }
}

// split + transpose W: g_wt*[n][k] = split(W[k][n])
__global__ void split_w_kernel(const float* __restrict__ W) {
    int nn = blockIdx.x;        // 0..255
    int k = threadIdx.x;        // 0..255
    float v = W[(size_t)k * F + nn];
    __nv_bfloat16 h = __float2bfloat16_rn(v);
    g_wth[nn * F + k] = h;
    g_wtl[nn * F + k] = __float2bfloat16_rn(v - __bfloat162float(h));
}

// ------------------------------------------------------------------
// bf16 split GEMM via mma.sync m16n8k16 (portable HMMA path)
// CTA: 128(m) x 128(n), 8 warps of 64x32, K staged in 4 chunks of 64
// ------------------------------------------------------------------
#define PAD 72                                 // bf16 per smem row (36 b32 banks)
#define TILE_BYTES (128 * PAD * 2)             // 18432
#define AH_OFF 0
#define AL_OFF (TILE_BYTES)
#define BH_OFF (2 * TILE_BYTES)
#define BL_OFF (3 * TILE_BYTES)
#define GSM_TOTAL (4 * TILE_BYTES)             // 73728

__device__ __forceinline__ void mma_bf16(float* d, const uint32_t* a, const uint32_t* b) {
    asm volatile(
        "mma.sync.aligned.m16n8k16.row.col.f32.bf16.bf16.f32 "
        "{%0,%1,%2,%3}, {%4,%5,%6,%7}, {%8,%9}, {%0,%1,%2,%3};\n"
        : "+f"(d[0]), "+f"(d[1]), "+f"(d[2]), "+f"(d[3])
        : "r"(a[0]), "r"(a[1]), "r"(a[2]), "r"(a[3]), "r"(b[0]), "r"(b[1]));
}

__global__ __launch_bounds__(256) void gemm_mma_kernel(int n) {
    extern __shared__ char smem[];
    int tid = threadIdx.x;
    int wid = tid >> 5;
    int lane = tid & 31;
    int gid = lane >> 2;        // 0..7
    int tig = lane & 3;         // 0..3
    int m0 = blockIdx.y * 128;
    int n0 = blockIdx.x * 128;
    int warpM = (wid >> 2) * 64;
    int warpN = (wid & 3) * 32;

    float acc[4][4][4];
#pragma unroll
    for (int i = 0; i < 4; i++)
#pragma unroll
        for (int j = 0; j < 4; j++)
#pragma unroll
            for (int q = 0; q < 4; q++) acc[i][j][q] = 0.f;

    for (int kc = 0; kc < 4; kc++) {
        int k0 = kc * 64;
        __syncthreads();   // protect previous stage reads
        // stage A (128 rows x 64 k) high+low
#pragma unroll
        for (int it = 0; it < 4; it++) {
            int g = it * 256 + tid;            // 0..1023
            int row = g >> 3;
            int c8 = (g & 7) * 8;
            int gm = m0 + row;
            uint4 vh = make_uint4(0, 0, 0, 0), vl = vh;
            if (gm < n) {
                vh = *(const uint4*)&g_xh[(size_t)gm * F + k0 + c8];
                vl = *(const uint4*)&g_xl[(size_t)gm * F + k0 + c8];
            }
            *(uint4*)(smem + AH_OFF + row * (PAD * 2) + c8 * 2) = vh;
            *(uint4*)(smem + AL_OFF + row * (PAD * 2) + c8 * 2) = vl;
        }
        // stage B (128 n-rows x 64 k) high+low from W^T
#pragma unroll
        for (int it = 0; it < 4; it++) {
            int g = it * 256 + tid;
            int row = g >> 3;
            int c8 = (g & 7) * 8;
            uint4 vh = *(const uint4*)&g_wth[(n0 + row) * F + k0 + c8];
            uint4 vl = *(const uint4*)&g_wtl[(n0 + row) * F + k0 + c8];
            *(uint4*)(smem + BH_OFF + row * (PAD * 2) + c8 * 2) = vh;
            *(uint4*)(smem + BL_OFF + row * (PAD * 2) + c8 * 2) = vl;
        }
        __syncthreads();

#pragma unroll
        for (int ks = 0; ks < 4; ks++) {
            int kb = ks * 16;
            uint32_t ah[4][4], al[4][4], bh[4][2], bl[4][2];
#pragma unroll
            for (int mi = 0; mi < 4; mi++) {
                int r0 = (warpM + mi * 16 + gid) * (PAD * 2);
                int r1 = r0 + 8 * (PAD * 2);
                int cA = (kb + tig * 2) * 2;
                ah[mi][0] = *(const uint32_t*)(smem + AH_OFF + r0 + cA);
                ah[mi][1] = *(const uint32_t*)(smem + AH_OFF + r1 + cA);
                ah[mi][2] = *(const uint32_t*)(smem + AH_OFF + r0 + cA + 16);
                ah[mi][3] = *(const uint32_t*)(smem + AH_OFF + r1 + cA + 16);
                al[mi][0] = *(const uint32_t*)(smem + AL_OFF + r0 + cA);
                al[mi][1] = *(const uint32_t*)(smem + AL_OFF + r1 + cA);
                al[mi][2] = *(const uint32_t*)(smem + AL_OFF + r0 + cA + 16);
                al[mi][3] = *(const uint32_t*)(smem + AL_OFF + r1 + cA + 16);
            }
#pragma unroll
            for (int nj = 0; nj < 4; nj++) {
                int r = (warpN + nj * 8 + gid) * (PAD * 2);
                int cB = (kb + tig * 2) * 2;
                bh[nj][0] = *(const uint32_t*)(smem + BH_OFF + r + cB);
                bh[nj][1] = *(const uint32_t*)(smem + BH_OFF + r + cB + 16);
                bl[nj][0] = *(const uint32_t*)(smem + BL_OFF + r + cB);
                bl[nj][1] = *(const uint32_t*)(smem + BL_OFF + r + cB + 16);
            }
#pragma unroll
            for (int mi = 0; mi < 4; mi++)
#pragma unroll
                for (int nj = 0; nj < 4; nj++) {
                    mma_bf16(acc[mi][nj], ah[mi], bh[nj]);
                    mma_bf16(acc[mi][nj], ah[mi], bl[nj]);
                    mma_bf16(acc[mi][nj], al[mi], bh[nj]);
                }
        }
    }

    // epilogue
#pragma unroll
    for (int mi = 0; mi < 4; mi++) {
        int r0 = m0 + warpM + mi * 16 + gid;
        int r1 = r0 + 8;
#pragma unroll
        for (int nj = 0; nj < 4; nj++) {
            int c = n0 + warpN + nj * 8 + tig * 2;
            if (r0 < n)
                *(float2*)&g_h[(size_t)r0 * F + c] = make_float2(acc[mi][nj][0], acc[mi][nj][1]);
            if (r1 < n)
                *(float2*)&g_h[(size_t)r1 * F + c] = make_float2(acc[mi][nj][2], acc[mi][nj][3]);
        }
    }
}

// ------------------------------------------------------------------
// probe edge_index dtype
// ------------------------------------------------------------------
__global__ void detect_kernel(const void* __restrict__ ei, int E) {
    if (threadIdx.x == 0 && blockIdx.x == 0) {
        const long long* p = (const long long*)ei;
        int ok = 1;
        int k = (E < 64) ? E : 64;
        for (int i = 0; i < k; i++) {
            long long v = p[i];
            if (v < 0 || v >= NMAX) ok = 0;
        }
        g_is64 = ok;
    }
}

__device__ __forceinline__ int load_idx(const void* ei, size_t pos, int is64) {
    if (is64) return (int)((const long long*)ei)[pos];
    return ((const int*)ei)[pos];
}

__global__ void zero_kernel(int n) {
    int i = blockIdx.x * blockDim.x + threadIdx.x;
    for (; i < n; i += gridDim.x * blockDim.x) {
        g_deg[i] = 0;
        g_fill[i] = 0;
        if (i < 2) g_stats[i] = 0.0;
    }
}

__global__ void deg_kernel(const void* __restrict__ ei, int E, int n) {
    int is64 = g_is64;
    int e = blockIdx.x * blockDim.x + threadIdx.x;
    for (; e < E; e += gridDim.x * blockDim.x) {
        int d = load_idx(ei, (size_t)E + e, is64);
        if ((unsigned)d < (unsigned)n) atomicAdd(&g_deg[d], 1);
    }
}

__global__ void dinv_kernel(int n) {
    int i = blockIdx.x * blockDim.x + threadIdx.x;
    if (i < n) g_dinv[i] = rsqrtf((float)(g_deg[i] + 1));
}

__global__ void scan1_kernel(int n) {
    int i = blockIdx.x * 512 + threadIdx.x;
    int v = (i < n) ? g_deg[i] : 0;
    for (int o = 16; o > 0; o >>= 1) v += __shfl_down_sync(~0u, v, o);
    __shared__ int wsum[16];
    int lane = threadIdx.x & 31, wid = threadIdx.x >> 5;
    if (lane == 0) wsum[wid] = v;
    __syncthreads();
    if (wid == 0) {
        int s = (lane < 16) ? wsum[lane] : 0;
        for (int o = 8; o > 0; o >>= 1) s += __shfl_down_sync(~0u, s, o);
        if (lane == 0) g_partial[blockIdx.x] = s;
    }
}

__global__ void scan2_kernel(int nb) {
    if (threadIdx.x == 0 && blockIdx.x == 0) {
        int acc = 0;
        for (int i = 0; i < nb; i++) { int v = g_partial[i]; g_partial[i] = acc; acc += v; }
    }
}

__global__ void scan3_kernel(int n) {
    int i = blockIdx.x * 512 + threadIdx.x;
    int v = (i < n) ? g_deg[i] : 0;
    int lane = threadIdx.x & 31, wid = threadIdx.x >> 5;
    int s = v;
    for (int o = 1; o < 32; o <<= 1) {
        int t = __shfl_up_sync(~0u, s, o);
        if (lane >= o) s += t;
    }
    __shared__ int wsum[16];
    if (lane == 31) wsum[wid] = s;
    __syncthreads();
    if (wid == 0) {
        int ws = (lane < 16) ? wsum[lane] : 0;
        for (int o = 1; o < 16; o <<= 1) {
            int t = __shfl_up_sync(~0u, ws, o);
            if (lane >= o) ws += t;
        }
        if (lane < 16) wsum[lane] = ws;
    }
    __syncthreads();
    int excl = s - v + (wid > 0 ? wsum[wid - 1] : 0) + g_partial[blockIdx.x];
    if (i < n)  g_ptr[i] = excl;
    if (i == n - 1) g_ptr[n] = excl + v;
}

__global__ void fill_kernel(const void* __restrict__ ei, int E, int n) {
    int is64 = g_is64;
    int e = blockIdx.x * blockDim.x + threadIdx.x;
    for (; e < E; e += gridDim.x * blockDim.x) {
        int s = load_idx(ei, (size_t)e, is64);
        int d = load_idx(ei, (size_t)E + e, is64);
        if ((unsigned)s >= (unsigned)n || (unsigned)d >= (unsigned)n) continue;
        int pos = g_ptr[d] + atomicAdd(&g_fill[d], 1);
        g_csrc[pos] = s;
    }
}

// ------------------------------------------------------------------
// aggregation (warp per node) + fused LN stats
// ------------------------------------------------------------------
__global__ __launch_bounds__(256) void aggregate_kernel(
    const float* __restrict__ bias, float* __restrict__ out, int n) {
    int wrp = threadIdx.x >> 5;
    int lane = threadIdx.x & 31;
    int node = blockIdx.x * 8 + wrp;
    bool valid = (node < n);

    float4 acc0 = make_float4(0.f, 0.f, 0.f, 0.f);
    float4 acc1 = make_float4(0.f, 0.f, 0.f, 0.f);

    if (valid) {
        float di = g_dinv[node];
        const float4* hr = (const float4*)&g_h[(size_t)node * F];
        float w = di * di;
        float4 a0 = hr[lane], a1 = hr[lane + 32];
        acc0 = make_float4(a0.x * w, a0.y * w, a0.z * w, a0.w * w);
        acc1 = make_float4(a1.x * w, a1.y * w, a1.z * w, a1.w * w);

        int beg = g_ptr[node], end = g_ptr[node + 1];
        int e = beg;
        for (; e + 1 < end; e += 2) {
            int s0 = g_csrc[e];
            int s1 = g_csrc[e + 1];
            float nm0 = g_dinv[s0] * di;
            float nm1 = g_dinv[s1] * di;
            const float4* h0 = (const float4*)&g_h[(size_t)s0 * F];
            const float4* h1 = (const float4*)&g_h[(size_t)s1 * F];
            float4 u0 = h0[lane], v0 = h0[lane + 32];
            float4 u1 = h1[lane], v1 = h1[lane + 32];
            acc0.x += u0.x * nm0; acc0.y += u0.y * nm0; acc0.z += u0.z * nm0; acc0.w += u0.w * nm0;
            acc1.x += v0.x * nm0; acc1.y += v0.y * nm0; acc1.z += v0.z * nm0; acc1.w += v0.w * nm0;
            acc0.x += u1.x * nm1; acc0.y += u1.y * nm1; acc0.z += u1.z * nm1; acc0.w += u1.w * nm1;
            acc1.x += v1.x * nm1; acc1.y += v1.y * nm1; acc1.z += v1.z * nm1; acc1.w += v1.w * nm1;
        }
        if (e < end) {
            int s0 = g_csrc[e];
            float nm0 = g_dinv[s0] * di;
            const float4* h0 = (const float4*)&g_h[(size_t)s0 * F];
            float4 u0 = h0[lane], v0 = h0[lane + 32];
            acc0.x += u0.x * nm0; acc0.y += u0.y * nm0; acc0.z += u0.z * nm0; acc0.w += u0.w * nm0;
            acc1.x += v0.x * nm0; acc1.y += v0.y * nm0; acc1.z += v0.z * nm0; acc1.w += v0.w * nm0;
        }
        float4 b0 = ((const float4*)bias)[lane];
        float4 b1 = ((const float4*)bias)[lane + 32];
        acc0.x += b0.x; acc0.y += b0.y; acc0.z += b0.z; acc0.w += b0.w;
        acc1.x += b1.x; acc1.y += b1.y; acc1.z += b1.z; acc1.w += b1.w;
        float4* orow = (float4*)&out[(size_t)node * F];
        orow[lane] = acc0;
        orow[lane + 32] = acc1;
    }

    float s  = acc0.x + acc0.y + acc0.z + acc0.w + acc1.x + acc1.y + acc1.z + acc1.w;
    float s2 = acc0.x * acc0.x + acc0.y * acc0.y + acc0.z * acc0.z + acc0.w * acc0.w
             + acc1.x * acc1.x + acc1.y * acc1.y + acc1.z * acc1.z + acc1.w * acc1.w;
    if (!valid) { s = 0.f; s2 = 0.f; }
    for (int o = 16; o > 0; o >>= 1) {
        s  += __shfl_down_sync(~0u, s, o);
        s2 += __shfl_down_sync(~0u, s2, o);
    }
    __shared__ float sh_s[8], sh_s2[8];
    if (lane == 0) { sh_s[wrp] = s; sh_s2[wrp] = s2; }
    __syncthreads();
    if (threadIdx.x == 0) {
        double a = 0.0, b = 0.0;
        for (int i = 0; i < 8; i++) { a += (double)sh_s[i]; b += (double)sh_s2[i]; }
        atomicAdd(&g_stats[0], a);
        atomicAdd(&g_stats[1], b);
    }
}

__global__ void finalize_kernel(float* __restrict__ out,
                                const float* __restrict__ lnw,
                                const float* __restrict__ lnb,
                                const float* __restrict__ pa, int M) {
    double mu = g_stats[0] / (double)M;
    double var = g_stats[1] / (double)M - mu * mu;
    if (var < 0.0) var = 0.0;
    float inv = 1.f / ((float)sqrt(var) + EPS);
    float fmu = (float)mu;
    float alpha = pa[0];
    int i = blockIdx.x * blockDim.x + threadIdx.x;
    for (; i < M; i += gridDim.x * blockDim.x) {
        int c = i & (F - 1);
        float y = (out[i] - fmu) * inv * lnw[c] + lnb[c];
        out[i] = (y >= 0.f) ? y : alpha * y;
    }
}

// ------------------------------------------------------------------
extern "C" void kernel_launch(void* const* d_in, const int* in_sizes, int n_in,
                              void* d_out, int out_size) {
    const float* x        = (const float*)d_in[0];
    const void*  ei       = d_in[1];
    const float* W        = (const float*)d_in[3];
    const float* conv_b   = (const float*)d_in[4];
    const float* lnw      = (const float*)d_in[5];
    const float* lnb      = (const float*)d_in[6];
    const float* pa       = (const float*)d_in[7];
    float* out = (float*)d_out;

    int n = in_sizes[0] / F;
    int E = in_sizes[1] / 2;
    int M = n * F;
    int nb = (n + 511) / 512;

    cudaFuncSetAttribute(gemm_mma_kernel,
                         cudaFuncAttributeMaxDynamicSharedMemorySize, GSM_TOTAL);

    detect_kernel<<<1, 32>>>(ei, E);
    zero_kernel<<<128, 512>>>(n);
    split_x_kernel<<<1024, 256>>>(x, M / 8);
    split_w_kernel<<<F, F>>>(W);
    gemm_mma_kernel<<<dim3(2, (n + 127) / 128), 256, GSM_TOTAL>>>(n);
    deg_kernel<<<1024, 256>>>(ei, E, n);
    dinv_kernel<<<(n + 255) / 256, 256>>>(n);
    scan1_kernel<<<nb, 512>>>(n);
    scan2_kernel<<<1, 32>>>(nb);
    scan3_kernel<<<nb, 512>>>(n);
    fill_kernel<<<1024, 256>>>(ei, E, n);
    aggregate_kernel<<<(n + 7) / 8, 256>>>(conv_b, out, n);
    finalize_kernel<<<512, 256>>>(out, lnw, lnb, pa, M);
}

// round 7
// speedup vs baseline: 1.7222x; 1.1388x over previous
#include <cuda_runtime.h>
#include <cuda_bf16.h>
#include <cuda_fp16.h>
#include <math.h>
#include <cstdint>

#define NMAX 50000
#define EMAX 800000
#define F 256
#define EPS 1e-5f

// ---- device scratch ----
__device__ float          g_h[(size_t)NMAX * F];
__device__ __half         g_h16[(size_t)NMAX * F];
__device__ __nv_bfloat16  g_xh[(size_t)NMAX * F];
__device__ __nv_bfloat16  g_xl[(size_t)NMAX * F];
__device__ __nv_bfloat16  g_wth[F * F];       // W^T high  [n][k]
__device__ __nv_bfloat16  g_wtl[F * F];       // W^T low
__device__ float  g_dinv[NMAX];
__device__ int    g_deg[NMAX];
__device__ int    g_fill[NMAX];
__device__ int    g_ptr[NMAX + 1];
__device__ int    g_csrc[EMAX];
__device__ int    g_partial[256];
__device__ double g_stats[2];
__device__ int    g_is64;

// ------------------------------------------------------------------
// split helpers
// ------------------------------------------------------------------
__device__ __forceinline__ uint32_t pack_bf16(float a, float b) {
    __nv_bfloat162 t;
    t.x = __float2bfloat16_rn(a);
    t.y = __float2bfloat16_rn(b);
    return *(uint32_t*)&t;
}
__device__ __forceinline__ void split8(const float* f, uint4& h, uint4& l) {
    float hv[8], lv[8];
#pragma unroll
    for (int j = 0; j < 8; j++) {
        __nv_bfloat16 b = __float2bfloat16_rn(f[j]);
        hv[j] = __bfloat162float(b);
        lv[j] = f[j] - hv[j];
    }
    h = make_uint4(pack_bf16(hv[0], hv[1]), pack_bf16(hv[2], hv[3]),
                   pack_bf16(hv[4], hv[5]), pack_bf16(hv[6], hv[7]));
    l = make_uint4(pack_bf16(lv[0], lv[1]), pack_bf16(lv[2], lv[3]),
                   pack_bf16(lv[4], lv[5]), pack_bf16(lv[6], lv[7]));
}

__global__ void split_x_kernel(const float* __restrict__ X, int n8) {
    int i = blockIdx.x * blockDim.x + threadIdx.x;
    for (; i < n8; i += gridDim.x * blockDim.x) {
        float f[8];
        float4 v0 = ((const float4*)X)[i * 2];
        float4 v1 = ((const float4*)X)[i * 2 + 1];
        f[0] = v0.x; f[1] = v0.y; f[2] = v0.z; f[3] = v0.w;
        f[4] = v1.x; f[5] = v1.y; f[6] = v1.z; f[7] = v1.w;
        uint4 h, l;
        split8(f, h, l);
        ((uint4*)g_xh)[i] = h;
        ((uint4*)g_xl)[i] = l;
    }
}

__global__ void split_w_kernel(const float* __restrict__ W) {
    int nn = blockIdx.x;
    int k = threadIdx.x;
    float v = W[(size_t)k * F + nn];
    __nv_bfloat16 h = __float2bfloat16_rn(v);
    g_wth[nn * F + k] = h;
    g_wtl[nn * F + k] = __float2bfloat16_rn(v - __bfloat162float(h));
}

// ------------------------------------------------------------------
// bf16 split GEMM via mma.sync m16n8k16
// ------------------------------------------------------------------
#define PAD 72
#define TILE_BYTES (128 * PAD * 2)
#define AH_OFF 0
#define AL_OFF (TILE_BYTES)
#define BH_OFF (2 * TILE_BYTES)
#define BL_OFF (3 * TILE_BYTES)
#define GSM_TOTAL (4 * TILE_BYTES)

__device__ __forceinline__ void mma_bf16(float* d, const uint32_t* a, const uint32_t* b) {
    asm volatile(
        "mma.sync.aligned.m16n8k16.row.col.f32.bf16.bf16.f32 "
        "{%0,%1,%2,%3}, {%4,%5,%6,%7}, {%8,%9}, {%0,%1,%2,%3};\n"
        : "+f"(d[0]), "+f"(d[1]), "+f"(d[2]), "+f"(d[3])
        : "r"(a[0]), "r"(a[1]), "r"(a[2]), "r"(a[3]), "r"(b[0]), "r"(b[1]));
}

__global__ __launch_bounds__(256) void gemm_mma_kernel(int n) {
    extern __shared__ char smem[];
    int tid = threadIdx.x;
    int wid = tid >> 5;
    int lane = tid & 31;
    int gid = lane >> 2;
    int tig = lane & 3;
    int m0 = blockIdx.y * 128;
    int n0 = blockIdx.x * 128;
    int warpM = (wid >> 2) * 64;
    int warpN = (wid & 3) * 32;

    float acc[4][4][4];
#pragma unroll
    for (int i = 0; i < 4; i++)
#pragma unroll
        for (int j = 0; j < 4; j++)
#pragma unroll
            for (int q = 0; q < 4; q++) acc[i][j][q] = 0.f;

    for (int kc = 0; kc < 4; kc++) {
        int k0 = kc * 64;
        __syncthreads();
#pragma unroll
        for (int it = 0; it < 4; it++) {
            int g = it * 256 + tid;
            int row = g >> 3;
            int c8 = (g & 7) * 8;
            int gm = m0 + row;
            uint4 vh = make_uint4(0, 0, 0, 0), vl = vh;
            if (gm < n) {
                vh = *(const uint4*)&g_xh[(size_t)gm * F + k0 + c8];
                vl = *(const uint4*)&g_xl[(size_t)gm * F + k0 + c8];
            }
            *(uint4*)(smem + AH_OFF + row * (PAD * 2) + c8 * 2) = vh;
            *(uint4*)(smem + AL_OFF + row * (PAD * 2) + c8 * 2) = vl;
        }
#pragma unroll
        for (int it = 0; it < 4; it++) {
            int g = it * 256 + tid;
            int row = g >> 3;
            int c8 = (g & 7) * 8;
            uint4 vh = *(const uint4*)&g_wth[(n0 + row) * F + k0 + c8];
            uint4 vl = *(const uint4*)&g_wtl[(n0 + row) * F + k0 + c8];
            *(uint4*)(smem + BH_OFF + row * (PAD * 2) + c8 * 2) = vh;
            *(uint4*)(smem + BL_OFF + row * (PAD * 2) + c8 * 2) = vl;
        }
        __syncthreads();

#pragma unroll
        for (int ks = 0; ks < 4; ks++) {
            int kb = ks * 16;
            uint32_t ah[4][4], al[4][4], bh[4][2], bl[4][2];
#pragma unroll
            for (int mi = 0; mi < 4; mi++) {
                int r0 = (warpM + mi * 16 + gid) * (PAD * 2);
                int r1 = r0 + 8 * (PAD * 2);
                int cA = (kb + tig * 2) * 2;
                ah[mi][0] = *(const uint32_t*)(smem + AH_OFF + r0 + cA);
                ah[mi][1] = *(const uint32_t*)(smem + AH_OFF + r1 + cA);
                ah[mi][2] = *(const uint32_t*)(smem + AH_OFF + r0 + cA + 16);
                ah[mi][3] = *(const uint32_t*)(smem + AH_OFF + r1 + cA + 16);
                al[mi][0] = *(const uint32_t*)(smem + AL_OFF + r0 + cA);
                al[mi][1] = *(const uint32_t*)(smem + AL_OFF + r1 + cA);
                al[mi][2] = *(const uint32_t*)(smem + AL_OFF + r0 + cA + 16);
                al[mi][3] = *(const uint32_t*)(smem + AL_OFF + r1 + cA + 16);
            }
#pragma unroll
            for (int nj = 0; nj < 4; nj++) {
                int r = (warpN + nj * 8 + gid) * (PAD * 2);
                int cB = (kb + tig * 2) * 2;
                bh[nj][0] = *(const uint32_t*)(smem + BH_OFF + r + cB);
                bh[nj][1] = *(const uint32_t*)(smem + BH_OFF + r + cB + 16);
                bl[nj][0] = *(const uint32_t*)(smem + BL_OFF + r + cB);
                bl[nj][1] = *(const uint32_t*)(smem + BL_OFF + r + cB + 16);
            }
#pragma unroll
            for (int mi = 0; mi < 4; mi++)
#pragma unroll
                for (int nj = 0; nj < 4; nj++) {
                    mma_bf16(acc[mi][nj], ah[mi], bh[nj]);
                    mma_bf16(acc[mi][nj], ah[mi], bl[nj]);
                    mma_bf16(acc[mi][nj], al[mi], bh[nj]);
                }
        }
    }

    // epilogue: fp32 + fp16 copies
#pragma unroll
    for (int mi = 0; mi < 4; mi++) {
        int r0 = m0 + warpM + mi * 16 + gid;
        int r1 = r0 + 8;
#pragma unroll
        for (int nj = 0; nj < 4; nj++) {
            int c = n0 + warpN + nj * 8 + tig * 2;
            if (r0 < n) {
                *(float2*)&g_h[(size_t)r0 * F + c] = make_float2(acc[mi][nj][0], acc[mi][nj][1]);
                *(__half2*)&g_h16[(size_t)r0 * F + c] =
                    __floats2half2_rn(acc[mi][nj][0], acc[mi][nj][1]);
            }
            if (r1 < n) {
                *(float2*)&g_h[(size_t)r1 * F + c] = make_float2(acc[mi][nj][2], acc[mi][nj][3]);
                *(__half2*)&g_h16[(size_t)r1 * F + c] =
                    __floats2half2_rn(acc[mi][nj][2], acc[mi][nj][3]);
            }
        }
    }
}

// ------------------------------------------------------------------
// edge dtype probe + CSR build
// ------------------------------------------------------------------
__global__ void detect_kernel(const void* __restrict__ ei, int E) {
    if (threadIdx.x == 0 && blockIdx.x == 0) {
        const long long* p = (const long long*)ei;
        int ok = 1;
        int k = (E < 64) ? E : 64;
        for (int i = 0; i < k; i++) {
            long long v = p[i];
            if (v < 0 || v >= NMAX) ok = 0;
        }
        g_is64 = ok;
    }
}

__device__ __forceinline__ int load_idx(const void* ei, size_t pos, int is64) {
    if (is64) return (int)((const long long*)ei)[pos];
    return ((const int*)ei)[pos];
}

__global__ void zero_kernel(int n) {
    int i = blockIdx.x * blockDim.x + threadIdx.x;
    for (; i < n; i += gridDim.x * blockDim.x) {
        g_deg[i] = 0;
        g_fill[i] = 0;
        if (i < 2) g_stats[i] = 0.0;
    }
}

__global__ void deg_kernel(const void* __restrict__ ei, int E, int n) {
    int is64 = g_is64;
    int e = blockIdx.x * blockDim.x + threadIdx.x;
    for (; e < E; e += gridDim.x * blockDim.x) {
        int d = load_idx(ei, (size_t)E + e, is64);
        if ((unsigned)d < (unsigned)n) atomicAdd(&g_deg[d], 1);
    }
}

__global__ void dinv_kernel(int n) {
    int i = blockIdx.x * blockDim.x + threadIdx.x;
    if (i < n) g_dinv[i] = rsqrtf((float)(g_deg[i] + 1));
}

__global__ void scan1_kernel(int n) {
    int i = blockIdx.x * 512 + threadIdx.x;
    int v = (i < n) ? g_deg[i] : 0;
    for (int o = 16; o > 0; o >>= 1) v += __shfl_down_sync(~0u, v, o);
    __shared__ int wsum[16];
    int lane = threadIdx.x & 31, wid = threadIdx.x >> 5;
    if (lane == 0) wsum[wid] = v;
    __syncthreads();
    if (wid == 0) {
        int s = (lane < 16) ? wsum[lane] : 0;
        for (int o = 8; o > 0; o >>= 1) s += __shfl_down_sync(~0u, s, o);
        if (lane == 0) g_partial[blockIdx.x] = s;
    }
}

__global__ void scan2_kernel(int nb) {
    if (threadIdx.x == 0 && blockIdx.x == 0) {
        int acc = 0;
        for (int i = 0; i < nb; i++) { int v = g_partial[i]; g_partial[i] = acc; acc += v; }
    }
}

__global__ void scan3_kernel(int n) {
    int i = blockIdx.x * 512 + threadIdx.x;
    int v = (i < n) ? g_deg[i] : 0;
    int lane = threadIdx.x & 31, wid = threadIdx.x >> 5;
    int s = v;
    for (int o = 1; o < 32; o <<= 1) {
        int t = __shfl_up_sync(~0u, s, o);
        if (lane >= o) s += t;
    }
    __shared__ int wsum[16];
    if (lane == 31) wsum[wid] = s;
    __syncthreads();
    if (wid == 0) {
        int ws = (lane < 16) ? wsum[lane] : 0;
        for (int o = 1; o < 16; o <<= 1) {
            int t = __shfl_up_sync(~0u, ws, o);
            if (lane >= o) ws += t;
        }
        if (lane < 16) wsum[lane] = ws;
    }
    __syncthreads();
    int excl = s - v + (wid > 0 ? wsum[wid - 1] : 0) + g_partial[blockIdx.x];
    if (i < n)  g_ptr[i] = excl;
    if (i == n - 1) g_ptr[n] = excl + v;
}

__global__ void fill_kernel(const void* __restrict__ ei, int E, int n) {
    int is64 = g_is64;
    int e = blockIdx.x * blockDim.x + threadIdx.x;
    for (; e < E; e += gridDim.x * blockDim.x) {
        int s = load_idx(ei, (size_t)e, is64);
        int d = load_idx(ei, (size_t)E + e, is64);
        if ((unsigned)s >= (unsigned)n || (unsigned)d >= (unsigned)n) continue;
        int pos = g_ptr[d] + atomicAdd(&g_fill[d], 1);
        g_csrc[pos] = s;
    }
}

// ------------------------------------------------------------------
// aggregation: warp per node, fp16 gathers (1 uint4/lane), fp32 accum
// lane owns features lane*8 .. lane*8+7
// ------------------------------------------------------------------
__global__ __launch_bounds__(256) void aggregate_kernel(
    const float* __restrict__ bias, float* __restrict__ out, int n) {
    int wrp = threadIdx.x >> 5;
    int lane = threadIdx.x & 31;
    int node = blockIdx.x * 8 + wrp;
    bool valid = (node < n);

    float acc[8];
#pragma unroll
    for (int q = 0; q < 8; q++) acc[q] = 0.f;

    if (valid) {
        float di = g_dinv[node];
        float w = di * di;
        // self term (fp32 h)
        {
            const float4* hr = (const float4*)&g_h[(size_t)node * F + lane * 8];
            float4 a0 = hr[0], a1 = hr[1];
            acc[0] = a0.x * w; acc[1] = a0.y * w; acc[2] = a0.z * w; acc[3] = a0.w * w;
            acc[4] = a1.x * w; acc[5] = a1.y * w; acc[6] = a1.z * w; acc[7] = a1.w * w;
        }
        int beg = g_ptr[node], end = g_ptr[node + 1];
        int e = beg;
        for (; e + 1 < end; e += 2) {
            int s0 = g_csrc[e];
            int s1 = g_csrc[e + 1];
            float nm0 = g_dinv[s0] * di;
            float nm1 = g_dinv[s1] * di;
            uint4 p0 = *(const uint4*)&g_h16[(size_t)s0 * F + lane * 8];
            uint4 p1 = *(const uint4*)&g_h16[(size_t)s1 * F + lane * 8];
            const __half2* q0 = (const __half2*)&p0;
            const __half2* q1 = (const __half2*)&p1;
#pragma unroll
            for (int j = 0; j < 4; j++) {
                float2 f0 = __half22float2(q0[j]);
                float2 f1 = __half22float2(q1[j]);
                acc[j * 2]     += f0.x * nm0 + f1.x * nm1;
                acc[j * 2 + 1] += f0.y * nm0 + f1.y * nm1;
            }
        }
        if (e < end) {
            int s0 = g_csrc[e];
            float nm0 = g_dinv[s0] * di;
            uint4 p0 = *(const uint4*)&g_h16[(size_t)s0 * F + lane * 8];
            const __half2* q0 = (const __half2*)&p0;
#pragma unroll
            for (int j = 0; j < 4; j++) {
                float2 f0 = __half22float2(q0[j]);
                acc[j * 2]     += f0.x * nm0;
                acc[j * 2 + 1] += f0.y * nm0;
            }
        }
        // bias + store
        const float4* bb = (const float4*)&bias[lane * 8];
        float4 b0 = bb[0], b1 = bb[1];
        acc[0] += b0.x; acc[1] += b0.y; acc[2] += b0.z; acc[3] += b0.w;
        acc[4] += b1.x; acc[5] += b1.y; acc[6] += b1.z; acc[7] += b1.w;
        float4* orow = (float4*)&out[(size_t)node * F + lane * 8];
        orow[0] = make_float4(acc[0], acc[1], acc[2], acc[3]);
        orow[1] = make_float4(acc[4], acc[5], acc[6], acc[7]);
    }

    // fused LN statistics
    float s = 0.f, s2 = 0.f;
#pragma unroll
    for (int q = 0; q < 8; q++) { s += acc[q]; s2 += acc[q] * acc[q]; }
    for (int o = 16; o > 0; o >>= 1) {
        s  += __shfl_down_sync(~0u, s, o);
        s2 += __shfl_down_sync(~0u, s2, o);
    }
    __shared__ float sh_s[8], sh_s2[8];
    if (lane == 0) { sh_s[wrp] = s; sh_s2[wrp] = s2; }
    __syncthreads();
    if (threadIdx.x == 0) {
        double a = 0.0, b = 0.0;
        for (int i = 0; i < 8; i++) { a += (double)sh_s[i]; b += (double)sh_s2[i]; }
        atomicAdd(&g_stats[0], a);
        atomicAdd(&g_stats[1], b);
    }
}

// ------------------------------------------------------------------
// finalize: layernorm + PReLU, float4 vectorized, in place
// ------------------------------------------------------------------
__global__ void finalize_kernel(float* __restrict__ out,
                                const float* __restrict__ lnw,
                                const float* __restrict__ lnb,
                                const float* __restrict__ pa, int M4) {
    int M = M4 * 4;
    double mu = g_stats[0] / (double)M;
    double var = g_stats[1] / (double)M - mu * mu;
    if (var < 0.0) var = 0.0;
    float inv = 1.f / ((float)sqrt(var) + EPS);
    float fmu = (float)mu;
    float alpha = pa[0];
    float4* o4 = (float4*)out;
    int i = blockIdx.x * blockDim.x + threadIdx.x;
    for (; i < M4; i += gridDim.x * blockDim.x) {
        int c = (i * 4) & (F - 1);
        float4 v = o4[i];
        float4 wv = *(const float4*)&lnw[c];
        float4 bv = *(const float4*)&lnb[c];
        float y0 = (v.x - fmu) * inv * wv.x + bv.x;
        float y1 = (v.y - fmu) * inv * wv.y + bv.y;
        float y2 = (v.z - fmu) * inv * wv.z + bv.z;
        float y3 = (v.w - fmu) * inv * wv.w + bv.w;
        o4[i] = make_float4(y0 >= 0.f ? y0 : alpha * y0,
                            y1 >= 0.f ? y1 : alpha * y1,
                            y2 >= 0.f ? y2 : alpha * y2,
                            y3 >= 0.f ? y3 : alpha * y3);
    }
}

// ------------------------------------------------------------------
extern "C" void kernel_launch(void* const* d_in, const int* in_sizes, int n_in,
                              void* d_out, int out_size) {
    const float* x        = (const float*)d_in[0];
    const void*  ei       = d_in[1];
    const float* W        = (const float*)d_in[3];
    const float* conv_b   = (const float*)d_in[4];
    const float* lnw      = (const float*)d_in[5];
    const float* lnb      = (const float*)d_in[6];
    const float* pa       = (const float*)d_in[7];
    float* out = (float*)d_out;

    int n = in_sizes[0] / F;
    int E = in_sizes[1] / 2;
    int M = n * F;
    int nb = (n + 511) / 512;

    cudaFuncSetAttribute(gemm_mma_kernel,
                         cudaFuncAttributeMaxDynamicSharedMemorySize, GSM_TOTAL);

    detect_kernel<<<1, 32>>>(ei, E);
    zero_kernel<<<128, 512>>>(n);
    split_x_kernel<<<1024, 256>>>(x, M / 8);
    split_w_kernel<<<F, F>>>(W);
    gemm_mma_kernel<<<dim3(2, (n + 127) / 128), 256, GSM_TOTAL>>>(n);
    deg_kernel<<<1024, 256>>>(ei, E, n);
    dinv_kernel<<<(n + 255) / 256, 256>>>(n);
    scan1_kernel<<<nb, 512>>>(n);
    scan2_kernel<<<1, 32>>>(nb);
    scan3_kernel<<<nb, 512>>>(n);
    fill_kernel<<<1024, 256>>>(ei, E, n);
    aggregate_kernel<<<(n + 7) / 8, 256>>>(conv_b, out, n);
    finalize_kernel<<<512, 256>>>(out, lnw, lnb, pa, M / 4);
}

// round 8
// speedup vs baseline: 1.9876x; 1.1541x over previous
#include <cuda_runtime.h>
#include <cuda_bf16.h>
#include <cuda_fp16.h>
#include <math.h>
#include <cstdint>

#define NMAX 50000
#define EMAX 800000
#define F 256
#define EPS 1e-5f

// ---- device scratch ----
__device__ float          g_h[(size_t)NMAX * F];
__device__ __half         g_h16[(size_t)NMAX * F];
__device__ __nv_bfloat16  g_xh[(size_t)NMAX * F];
__device__ __nv_bfloat16  g_xl[(size_t)NMAX * F];
__device__ __nv_bfloat16  g_wth[F * F];       // W^T high  [n][k]
__device__ __nv_bfloat16  g_wtl[F * F];       // W^T low
__device__ float  g_dinv[NMAX];
__device__ int    g_deg[NMAX];
__device__ int    g_fill[NMAX];
__device__ int    g_ptr[NMAX + 1];
__device__ int    g_csrc[EMAX];
__device__ int    g_partial[256];
__device__ double g_stats[2];
__device__ int    g_is64;

// ------------------------------------------------------------------
// split helpers
// ------------------------------------------------------------------
__device__ __forceinline__ uint32_t pack_bf16(float a, float b) {
    __nv_bfloat162 t;
    t.x = __float2bfloat16_rn(a);
    t.y = __float2bfloat16_rn(b);
    return *(uint32_t*)&t;
}
__device__ __forceinline__ void split8(const float* f, uint4& h, uint4& l) {
    float hv[8], lv[8];
#pragma unroll
    for (int j = 0; j < 8; j++) {
        __nv_bfloat16 b = __float2bfloat16_rn(f[j]);
        hv[j] = __bfloat162float(b);
        lv[j] = f[j] - hv[j];
    }
    h = make_uint4(pack_bf16(hv[0], hv[1]), pack_bf16(hv[2], hv[3]),
                   pack_bf16(hv[4], hv[5]), pack_bf16(hv[6], hv[7]));
    l = make_uint4(pack_bf16(lv[0], lv[1]), pack_bf16(lv[2], lv[3]),
                   pack_bf16(lv[4], lv[5]), pack_bf16(lv[6], lv[7]));
}

__global__ void split_x_kernel(const float* __restrict__ X, int n8) {
    int i = blockIdx.x * blockDim.x + threadIdx.x;
    for (; i < n8; i += gridDim.x * blockDim.x) {
        float f[8];
        float4 v0 = ((const float4*)X)[i * 2];
        float4 v1 = ((const float4*)X)[i * 2 + 1];
        f[0] = v0.x; f[1] = v0.y; f[2] = v0.z; f[3] = v0.w;
        f[4] = v1.x; f[5] = v1.y; f[6] = v1.z; f[7] = v1.w;
        uint4 h, l;
        split8(f, h, l);
        ((uint4*)g_xh)[i] = h;
        ((uint4*)g_xl)[i] = l;
    }
}

__global__ void split_w_kernel(const float* __restrict__ W) {
    int nn = blockIdx.x;
    int k = threadIdx.x;
    float v = W[(size_t)k * F + nn];
    __nv_bfloat16 h = __float2bfloat16_rn(v);
    g_wth[nn * F + k] = h;
    g_wtl[nn * F + k] = __float2bfloat16_rn(v - __bfloat162float(h));
}

// ------------------------------------------------------------------
// bf16 split GEMM via mma.sync m16n8k16
// ------------------------------------------------------------------
#define PAD 72
#define TILE_BYTES (128 * PAD * 2)
#define AH_OFF 0
#define AL_OFF (TILE_BYTES)
#define BH_OFF (2 * TILE_BYTES)
#define BL_OFF (3 * TILE_BYTES)
#define GSM_TOTAL (4 * TILE_BYTES)

__device__ __forceinline__ void mma_bf16(float* d, const uint32_t* a, const uint32_t* b) {
    asm volatile(
        "mma.sync.aligned.m16n8k16.row.col.f32.bf16.bf16.f32 "
        "{%0,%1,%2,%3}, {%4,%5,%6,%7}, {%8,%9}, {%0,%1,%2,%3};\n"
        : "+f"(d[0]), "+f"(d[1]), "+f"(d[2]), "+f"(d[3])
        : "r"(a[0]), "r"(a[1]), "r"(a[2]), "r"(a[3]), "r"(b[0]), "r"(b[1]));
}

__global__ __launch_bounds__(256) void gemm_mma_kernel(int n) {
    extern __shared__ char smem[];
    int tid = threadIdx.x;
    int wid = tid >> 5;
    int lane = tid & 31;
    int gid = lane >> 2;
    int tig = lane & 3;
    int m0 = blockIdx.y * 128;
    int n0 = blockIdx.x * 128;
    int warpM = (wid >> 2) * 64;
    int warpN = (wid & 3) * 32;

    float acc[4][4][4];
#pragma unroll
    for (int i = 0; i < 4; i++)
#pragma unroll
        for (int j = 0; j < 4; j++)
#pragma unroll
            for (int q = 0; q < 4; q++) acc[i][j][q] = 0.f;

    for (int kc = 0; kc < 4; kc++) {
        int k0 = kc * 64;
        __syncthreads();
#pragma unroll
        for (int it = 0; it < 4; it++) {
            int g = it * 256 + tid;
            int row = g >> 3;
            int c8 = (g & 7) * 8;
            int gm = m0 + row;
            uint4 vh = make_uint4(0, 0, 0, 0), vl = vh;
            if (gm < n) {
                vh = *(const uint4*)&g_xh[(size_t)gm * F + k0 + c8];
                vl = *(const uint4*)&g_xl[(size_t)gm * F + k0 + c8];
            }
            *(uint4*)(smem + AH_OFF + row * (PAD * 2) + c8 * 2) = vh;
            *(uint4*)(smem + AL_OFF + row * (PAD * 2) + c8 * 2) = vl;
        }
#pragma unroll
        for (int it = 0; it < 4; it++) {
            int g = it * 256 + tid;
            int row = g >> 3;
            int c8 = (g & 7) * 8;
            uint4 vh = *(const uint4*)&g_wth[(n0 + row) * F + k0 + c8];
            uint4 vl = *(const uint4*)&g_wtl[(n0 + row) * F + k0 + c8];
            *(uint4*)(smem + BH_OFF + row * (PAD * 2) + c8 * 2) = vh;
            *(uint4*)(smem + BL_OFF + row * (PAD * 2) + c8 * 2) = vl;
        }
        __syncthreads();

#pragma unroll
        for (int ks = 0; ks < 4; ks++) {
            int kb = ks * 16;
            uint32_t ah[4][4], al[4][4], bh[4][2], bl[4][2];
#pragma unroll
            for (int mi = 0; mi < 4; mi++) {
                int r0 = (warpM + mi * 16 + gid) * (PAD * 2);
                int r1 = r0 + 8 * (PAD * 2);
                int cA = (kb + tig * 2) * 2;
                ah[mi][0] = *(const uint32_t*)(smem + AH_OFF + r0 + cA);
                ah[mi][1] = *(const uint32_t*)(smem + AH_OFF + r1 + cA);
                ah[mi][2] = *(const uint32_t*)(smem + AH_OFF + r0 + cA + 16);
                ah[mi][3] = *(const uint32_t*)(smem + AH_OFF + r1 + cA + 16);
                al[mi][0] = *(const uint32_t*)(smem + AL_OFF + r0 + cA);
                al[mi][1] = *(const uint32_t*)(smem + AL_OFF + r1 + cA);
                al[mi][2] = *(const uint32_t*)(smem + AL_OFF + r0 + cA + 16);
                al[mi][3] = *(const uint32_t*)(smem + AL_OFF + r1 + cA + 16);
            }
#pragma unroll
            for (int nj = 0; nj < 4; nj++) {
                int r = (warpN + nj * 8 + gid) * (PAD * 2);
                int cB = (kb + tig * 2) * 2;
                bh[nj][0] = *(const uint32_t*)(smem + BH_OFF + r + cB);
                bh[nj][1] = *(const uint32_t*)(smem + BH_OFF + r + cB + 16);
                bl[nj][0] = *(const uint32_t*)(smem + BL_OFF + r + cB);
                bl[nj][1] = *(const uint32_t*)(smem + BL_OFF + r + cB + 16);
            }
#pragma unroll
            for (int mi = 0; mi < 4; mi++)
#pragma unroll
                for (int nj = 0; nj < 4; nj++) {
                    mma_bf16(acc[mi][nj], ah[mi], bh[nj]);
                    mma_bf16(acc[mi][nj], ah[mi], bl[nj]);
                    mma_bf16(acc[mi][nj], al[mi], bh[nj]);
                }
        }
    }

    // epilogue: fp32 + fp16 copies
#pragma unroll
    for (int mi = 0; mi < 4; mi++) {
        int r0 = m0 + warpM + mi * 16 + gid;
        int r1 = r0 + 8;
#pragma unroll
        for (int nj = 0; nj < 4; nj++) {
            int c = n0 + warpN + nj * 8 + tig * 2;
            if (r0 < n) {
                *(float2*)&g_h[(size_t)r0 * F + c] = make_float2(acc[mi][nj][0], acc[mi][nj][1]);
                *(__half2*)&g_h16[(size_t)r0 * F + c] =
                    __floats2half2_rn(acc[mi][nj][0], acc[mi][nj][1]);
            }
            if (r1 < n) {
                *(float2*)&g_h[(size_t)r1 * F + c] = make_float2(acc[mi][nj][2], acc[mi][nj][3]);
                *(__half2*)&g_h16[(size_t)r1 * F + c] =
                    __floats2half2_rn(acc[mi][nj][2], acc[mi][nj][3]);
            }
        }
    }
}

// ------------------------------------------------------------------
// edge dtype probe + CSR build
// ------------------------------------------------------------------
__global__ void detect_kernel(const void* __restrict__ ei, int E) {
    if (threadIdx.x == 0 && blockIdx.x == 0) {
        const long long* p = (const long long*)ei;
        int ok = 1;
        int k = (E < 64) ? E : 64;
        for (int i = 0; i < k; i++) {
            long long v = p[i];
            if (v < 0 || v >= NMAX) ok = 0;
        }
        g_is64 = ok;
    }
}

__device__ __forceinline__ int load_idx(const void* ei, size_t pos, int is64) {
    if (is64) return (int)((const long long*)ei)[pos];
    return ((const int*)ei)[pos];
}

__global__ void zero_kernel(int n) {
    int i = blockIdx.x * blockDim.x + threadIdx.x;
    for (; i < n; i += gridDim.x * blockDim.x) {
        g_deg[i] = 0;
        g_fill[i] = 0;
        if (i < 2) g_stats[i] = 0.0;
    }
}

__global__ void deg_kernel(const void* __restrict__ ei, int E, int n) {
    int is64 = g_is64;
    int e = blockIdx.x * blockDim.x + threadIdx.x;
    for (; e < E; e += gridDim.x * blockDim.x) {
        int d = load_idx(ei, (size_t)E + e, is64);
        if ((unsigned)d < (unsigned)n) atomicAdd(&g_deg[d], 1);
    }
}

__global__ void dinv_kernel(int n) {
    int i = blockIdx.x * blockDim.x + threadIdx.x;
    if (i < n) g_dinv[i] = rsqrtf((float)(g_deg[i] + 1));
}

__global__ void scan1_kernel(int n) {
    int i = blockIdx.x * 512 + threadIdx.x;
    int v = (i < n) ? g_deg[i] : 0;
    for (int o = 16; o > 0; o >>= 1) v += __shfl_down_sync(~0u, v, o);
    __shared__ int wsum[16];
    int lane = threadIdx.x & 31, wid = threadIdx.x >> 5;
    if (lane == 0) wsum[wid] = v;
    __syncthreads();
    if (wid == 0) {
        int s = (lane < 16) ? wsum[lane] : 0;
        for (int o = 8; o > 0; o >>= 1) s += __shfl_down_sync(~0u, s, o);
        if (lane == 0) g_partial[blockIdx.x] = s;
    }
}

__global__ void scan2_kernel(int nb) {
    if (threadIdx.x == 0 && blockIdx.x == 0) {
        int acc = 0;
        for (int i = 0; i < nb; i++) { int v = g_partial[i]; g_partial[i] = acc; acc += v; }
    }
}

__global__ void scan3_kernel(int n) {
    int i = blockIdx.x * 512 + threadIdx.x;
    int v = (i < n) ? g_deg[i] : 0;
    int lane = threadIdx.x & 31, wid = threadIdx.x >> 5;
    int s = v;
    for (int o = 1; o < 32; o <<= 1) {
        int t = __shfl_up_sync(~0u, s, o);
        if (lane >= o) s += t;
    }
    __shared__ int wsum[16];
    if (lane == 31) wsum[wid] = s;
    __syncthreads();
    if (wid == 0) {
        int ws = (lane < 16) ? wsum[lane] : 0;
        for (int o = 1; o < 16; o <<= 1) {
            int t = __shfl_up_sync(~0u, ws, o);
            if (lane >= o) ws += t;
        }
        if (lane < 16) wsum[lane] = ws;
    }
    __syncthreads();
    int excl = s - v + (wid > 0 ? wsum[wid - 1] : 0) + g_partial[blockIdx.x];
    if (i < n)  g_ptr[i] = excl;
    if (i == n - 1) g_ptr[n] = excl + v;
}

__global__ void fill_kernel(const void* __restrict__ ei, int E, int n) {
    int is64 = g_is64;
    int e = blockIdx.x * blockDim.x + threadIdx.x;
    for (; e < E; e += gridDim.x * blockDim.x) {
        int s = load_idx(ei, (size_t)e, is64);
        int d = load_idx(ei, (size_t)E + e, is64);
        if ((unsigned)s >= (unsigned)n || (unsigned)d >= (unsigned)n) continue;
        int pos = g_ptr[d] + atomicAdd(&g_fill[d], 1);
        g_csrc[pos] = s;
    }
}

// ------------------------------------------------------------------
// aggregation: warp per node, fp16 gathers, unroll x4, fp32 accum
// ------------------------------------------------------------------
__device__ __forceinline__ void acc_row(float* acc, const uint4& p, float nm) {
    const __half2* q = (const __half2*)&p;
#pragma unroll
    for (int j = 0; j < 4; j++) {
        float2 f = __half22float2(q[j]);
        acc[j * 2]     += f.x * nm;
        acc[j * 2 + 1] += f.y * nm;
    }
}

__global__ __launch_bounds__(256) void aggregate_kernel(
    const float* __restrict__ bias, float* __restrict__ out, int n) {
    int wrp = threadIdx.x >> 5;
    int lane = threadIdx.x & 31;
    int node = blockIdx.x * 8 + wrp;
    bool valid = (node < n);

    float acc[8];
#pragma unroll
    for (int q = 0; q < 8; q++) acc[q] = 0.f;

    if (valid) {
        float di = g_dinv[node];
        float w = di * di;
        {
            const float4* hr = (const float4*)&g_h[(size_t)node * F + lane * 8];
            float4 a0 = hr[0], a1 = hr[1];
            acc[0] = a0.x * w; acc[1] = a0.y * w; acc[2] = a0.z * w; acc[3] = a0.w * w;
            acc[4] = a1.x * w; acc[5] = a1.y * w; acc[6] = a1.z * w; acc[7] = a1.w * w;
        }
        int beg = g_ptr[node], end = g_ptr[node + 1];
        int e = beg;
        for (; e + 3 < end; e += 4) {
            int s0 = g_csrc[e],     s1 = g_csrc[e + 1];
            int s2 = g_csrc[e + 2], s3 = g_csrc[e + 3];
            float nm0 = g_dinv[s0] * di, nm1 = g_dinv[s1] * di;
            float nm2 = g_dinv[s2] * di, nm3 = g_dinv[s3] * di;
            uint4 p0 = *(const uint4*)&g_h16[(size_t)s0 * F + lane * 8];
            uint4 p1 = *(const uint4*)&g_h16[(size_t)s1 * F + lane * 8];
            uint4 p2 = *(const uint4*)&g_h16[(size_t)s2 * F + lane * 8];
            uint4 p3 = *(const uint4*)&g_h16[(size_t)s3 * F + lane * 8];
            acc_row(acc, p0, nm0);
            acc_row(acc, p1, nm1);
            acc_row(acc, p2, nm2);
            acc_row(acc, p3, nm3);
        }
        for (; e < end; e++) {
            int s0 = g_csrc[e];
            float nm0 = g_dinv[s0] * di;
            uint4 p0 = *(const uint4*)&g_h16[(size_t)s0 * F + lane * 8];
            acc_row(acc, p0, nm0);
        }
        const float4* bb = (const float4*)&bias[lane * 8];
        float4 b0 = bb[0], b1 = bb[1];
        acc[0] += b0.x; acc[1] += b0.y; acc[2] += b0.z; acc[3] += b0.w;
        acc[4] += b1.x; acc[5] += b1.y; acc[6] += b1.z; acc[7] += b1.w;
        float4* orow = (float4*)&out[(size_t)node * F + lane * 8];
        orow[0] = make_float4(acc[0], acc[1], acc[2], acc[3]);
        orow[1] = make_float4(acc[4], acc[5], acc[6], acc[7]);
    }

    // fused LN statistics
    float s = 0.f, s2 = 0.f;
#pragma unroll
    for (int q = 0; q < 8; q++) { s += acc[q]; s2 += acc[q] * acc[q]; }
    for (int o = 16; o > 0; o >>= 1) {
        s  += __shfl_down_sync(~0u, s, o);
        s2 += __shfl_down_sync(~0u, s2, o);
    }
    __shared__ float sh_s[8], sh_s2[8];
    if (lane == 0) { sh_s[wrp] = s; sh_s2[wrp] = s2; }
    __syncthreads();
    if (threadIdx.x == 0) {
        double a = 0.0, b = 0.0;
        for (int i = 0; i < 8; i++) { a += (double)sh_s[i]; b += (double)sh_s2[i]; }
        atomicAdd(&g_stats[0], a);
        atomicAdd(&g_stats[1], b);
    }
}

// ------------------------------------------------------------------
// finalize: layernorm + PReLU, float4 vectorized, in place
// ------------------------------------------------------------------
__global__ void finalize_kernel(float* __restrict__ out,
                                const float* __restrict__ lnw,
                                const float* __restrict__ lnb,
                                const float* __restrict__ pa, int M4) {
    int M = M4 * 4;
    double mu = g_stats[0] / (double)M;
    double var = g_stats[1] / (double)M - mu * mu;
    if (var < 0.0) var = 0.0;
    float inv = 1.f / ((float)sqrt(var) + EPS);
    float fmu = (float)mu;
    float alpha = pa[0];
    float4* o4 = (float4*)out;
    int i = blockIdx.x * blockDim.x + threadIdx.x;
    for (; i < M4; i += gridDim.x * blockDim.x) {
        int c = (i * 4) & (F - 1);
        float4 v = o4[i];
        float4 wv = *(const float4*)&lnw[c];
        float4 bv = *(const float4*)&lnb[c];
        float y0 = (v.x - fmu) * inv * wv.x + bv.x;
        float y1 = (v.y - fmu) * inv * wv.y + bv.y;
        float y2 = (v.z - fmu) * inv * wv.z + bv.z;
        float y3 = (v.w - fmu) * inv * wv.w + bv.w;
        o4[i] = make_float4(y0 >= 0.f ? y0 : alpha * y0,
                            y1 >= 0.f ? y1 : alpha * y1,
                            y2 >= 0.f ? y2 : alpha * y2,
                            y3 >= 0.f ? y3 : alpha * y3);
    }
}

// ------------------------------------------------------------------
extern "C" void kernel_launch(void* const* d_in, const int* in_sizes, int n_in,
                              void* d_out, int out_size) {
    const float* x        = (const float*)d_in[0];
    const void*  ei       = d_in[1];
    const float* W        = (const float*)d_in[3];
    const float* conv_b   = (const float*)d_in[4];
    const float* lnw      = (const float*)d_in[5];
    const float* lnb      = (const float*)d_in[6];
    const float* pa       = (const float*)d_in[7];
    float* out = (float*)d_out;

    int n = in_sizes[0] / F;
    int E = in_sizes[1] / 2;
    int M = n * F;
    int nb = (n + 511) / 512;

    cudaFuncSetAttribute(gemm_mma_kernel,
                         cudaFuncAttributeMaxDynamicSharedMemorySize, GSM_TOTAL);

    // side stream + fork/join events (created per call; never destroyed so an
    // in-progress capture is never invalidated — only 2 non-replayed calls)
    cudaStream_t s1;
    cudaStreamCreateWithFlags(&s1, cudaStreamNonBlocking);
    cudaEvent_t eFork, eJoin;
    cudaEventCreateWithFlags(&eFork, cudaEventDisableTiming);
    cudaEventCreateWithFlags(&eJoin, cudaEventDisableTiming);

    // common prologue on main stream
    detect_kernel<<<1, 32>>>(ei, E);
    zero_kernel<<<128, 512>>>(n);

    // fork: CSR branch on s1
    cudaEventRecord(eFork, 0);
    cudaStreamWaitEvent(s1, eFork, 0);
    deg_kernel<<<1024, 256, 0, s1>>>(ei, E, n);
    dinv_kernel<<<(n + 255) / 256, 256, 0, s1>>>(n);
    scan1_kernel<<<nb, 512, 0, s1>>>(n);
    scan2_kernel<<<1, 32, 0, s1>>>(nb);
    scan3_kernel<<<nb, 512, 0, s1>>>(n);
    fill_kernel<<<1024, 256, 0, s1>>>(ei, E, n);
    cudaEventRecord(eJoin, s1);

    // GEMM branch on main stream (concurrent with CSR branch)
    split_x_kernel<<<1024, 256>>>(x, M / 8);
    split_w_kernel<<<F, F>>>(W);
    gemm_mma_kernel<<<dim3(2, (n + 127) / 128), 256, GSM_TOTAL>>>(n);

    // join, then aggregate + finalize
    cudaStreamWaitEvent(0, eJoin, 0);
    aggregate_kernel<<<(n + 7) / 8, 256>>>(conv_b, out, n);
    finalize_kernel<<<512, 256>>>(out, lnw, lnb, pa, M / 4);
}

// round 9
// speedup vs baseline: 2.2031x; 1.1084x over previous
#include <cuda_runtime.h>
#include <cuda_bf16.h>
#include <cuda_fp16.h>
#include <math.h>
#include <cstdint>

#define NMAX 50000
#define EMAX 800000
#define F 256
#define EPS 1e-5f

// ---- device scratch ----
__device__ __half         g_h16[(size_t)NMAX * F];
__device__ __nv_bfloat16  g_xh[(size_t)NMAX * F];
__device__ __nv_bfloat16  g_xl[(size_t)NMAX * F];
__device__ __nv_bfloat16  g_wth[F * F];       // W^T high  [n][k]
__device__ __nv_bfloat16  g_wtl[F * F];       // W^T low
__device__ float  g_dinv[NMAX];
__device__ int    g_deg[NMAX];
__device__ int    g_fill[NMAX];
__device__ int    g_ptr[NMAX + 1];
__device__ int    g_csrc[EMAX];
__device__ int    g_partial[256];
__device__ double g_stats[2];

// ------------------------------------------------------------------
// block-local edge dtype probe: int64 storage => first 64 longlongs in [0,NMAX)
// ------------------------------------------------------------------
__device__ __forceinline__ int probe_is64(const void* ei, int E) {
    __shared__ int ok_sh;
    if (threadIdx.x == 0) ok_sh = 1;
    __syncthreads();
    int k = (E < 64) ? E : 64;
    if ((int)threadIdx.x < k) {
        long long v = ((const long long*)ei)[threadIdx.x];
        if (v < 0 || v >= NMAX) ok_sh = 0;
    }
    __syncthreads();
    return ok_sh;
}

__device__ __forceinline__ int load_idx(const void* ei, size_t pos, int is64) {
    if (is64) return (int)((const long long*)ei)[pos];
    return ((const int*)ei)[pos];
}

// ------------------------------------------------------------------
// split helpers
// ------------------------------------------------------------------
__device__ __forceinline__ uint32_t pack_bf16(float a, float b) {
    __nv_bfloat162 t;
    t.x = __float2bfloat16_rn(a);
    t.y = __float2bfloat16_rn(b);
    return *(uint32_t*)&t;
}
__device__ __forceinline__ void split8(const float* f, uint4& h, uint4& l) {
    float hv[8], lv[8];
#pragma unroll
    for (int j = 0; j < 8; j++) {
        __nv_bfloat16 b = __float2bfloat16_rn(f[j]);
        hv[j] = __bfloat162float(b);
        lv[j] = f[j] - hv[j];
    }
    h = make_uint4(pack_bf16(hv[0], hv[1]), pack_bf16(hv[2], hv[3]),
                   pack_bf16(hv[4], hv[5]), pack_bf16(hv[6], hv[7]));
    l = make_uint4(pack_bf16(lv[0], lv[1]), pack_bf16(lv[2], lv[3]),
                   pack_bf16(lv[4], lv[5]), pack_bf16(lv[6], lv[7]));
}

__global__ void split_x_kernel(const float* __restrict__ X, int n8) {
    int i = blockIdx.x * blockDim.x + threadIdx.x;
    for (; i < n8; i += gridDim.x * blockDim.x) {
        float f[8];
        float4 v0 = ((const float4*)X)[i * 2];
        float4 v1 = ((const float4*)X)[i * 2 + 1];
        f[0] = v0.x; f[1] = v0.y; f[2] = v0.z; f[3] = v0.w;
        f[4] = v1.x; f[5] = v1.y; f[6] = v1.z; f[7] = v1.w;
        uint4 h, l;
        split8(f, h, l);
        ((uint4*)g_xh)[i] = h;
        ((uint4*)g_xl)[i] = l;
    }
}

__global__ void split_w_kernel(const float* __restrict__ W) {
    int nn = blockIdx.x;
    int k = threadIdx.x;
    float v = W[(size_t)k * F + nn];
    __nv_bfloat16 h = __float2bfloat16_rn(v);
    g_wth[nn * F + k] = h;
    g_wtl[nn * F + k] = __float2bfloat16_rn(v - __bfloat162float(h));
}

// ------------------------------------------------------------------
// bf16 split GEMM via mma.sync m16n8k16 -> fp16 output only
// ------------------------------------------------------------------
#define PAD 72
#define TILE_BYTES (128 * PAD * 2)
#define AH_OFF 0
#define AL_OFF (TILE_BYTES)
#define BH_OFF (2 * TILE_BYTES)
#define BL_OFF (3 * TILE_BYTES)
#define GSM_TOTAL (4 * TILE_BYTES)

__device__ __forceinline__ void mma_bf16(float* d, const uint32_t* a, const uint32_t* b) {
    asm volatile(
        "mma.sync.aligned.m16n8k16.row.col.f32.bf16.bf16.f32 "
        "{%0,%1,%2,%3}, {%4,%5,%6,%7}, {%8,%9}, {%0,%1,%2,%3};\n"
        : "+f"(d[0]), "+f"(d[1]), "+f"(d[2]), "+f"(d[3])
        : "r"(a[0]), "r"(a[1]), "r"(a[2]), "r"(a[3]), "r"(b[0]), "r"(b[1]));
}

__global__ __launch_bounds__(256) void gemm_mma_kernel(int n) {
    extern __shared__ char smem[];
    int tid = threadIdx.x;
    int wid = tid >> 5;
    int lane = tid & 31;
    int gid = lane >> 2;
    int tig = lane & 3;
    int m0 = blockIdx.y * 128;
    int n0 = blockIdx.x * 128;
    int warpM = (wid >> 2) * 64;
    int warpN = (wid & 3) * 32;

    float acc[4][4][4];
#pragma unroll
    for (int i = 0; i < 4; i++)
#pragma unroll
        for (int j = 0; j < 4; j++)
#pragma unroll
            for (int q = 0; q < 4; q++) acc[i][j][q] = 0.f;

    for (int kc = 0; kc < 4; kc++) {
        int k0 = kc * 64;
        __syncthreads();
#pragma unroll
        for (int it = 0; it < 4; it++) {
            int g = it * 256 + tid;
            int row = g >> 3;
            int c8 = (g & 7) * 8;
            int gm = m0 + row;
            uint4 vh = make_uint4(0, 0, 0, 0), vl = vh;
            if (gm < n) {
                vh = *(const uint4*)&g_xh[(size_t)gm * F + k0 + c8];
                vl = *(const uint4*)&g_xl[(size_t)gm * F + k0 + c8];
            }
            *(uint4*)(smem + AH_OFF + row * (PAD * 2) + c8 * 2) = vh;
            *(uint4*)(smem + AL_OFF + row * (PAD * 2) + c8 * 2) = vl;
        }
#pragma unroll
        for (int it = 0; it < 4; it++) {
            int g = it * 256 + tid;
            int row = g >> 3;
            int c8 = (g & 7) * 8;
            uint4 vh = *(const uint4*)&g_wth[(n0 + row) * F + k0 + c8];
            uint4 vl = *(const uint4*)&g_wtl[(n0 + row) * F + k0 + c8];
            *(uint4*)(smem + BH_OFF + row * (PAD * 2) + c8 * 2) = vh;
            *(uint4*)(smem + BL_OFF + row * (PAD * 2) + c8 * 2) = vl;
        }
        __syncthreads();

#pragma unroll
        for (int ks = 0; ks < 4; ks++) {
            int kb = ks * 16;
            uint32_t ah[4][4], al[4][4], bh[4][2], bl[4][2];
#pragma unroll
            for (int mi = 0; mi < 4; mi++) {
                int r0 = (warpM + mi * 16 + gid) * (PAD * 2);
                int r1 = r0 + 8 * (PAD * 2);
                int cA = (kb + tig * 2) * 2;
                ah[mi][0] = *(const uint32_t*)(smem + AH_OFF + r0 + cA);
                ah[mi][1] = *(const uint32_t*)(smem + AH_OFF + r1 + cA);
                ah[mi][2] = *(const uint32_t*)(smem + AH_OFF + r0 + cA + 16);
                ah[mi][3] = *(const uint32_t*)(smem + AH_OFF + r1 + cA + 16);
                al[mi][0] = *(const uint32_t*)(smem + AL_OFF + r0 + cA);
                al[mi][1] = *(const uint32_t*)(smem + AL_OFF + r1 + cA);
                al[mi][2] = *(const uint32_t*)(smem + AL_OFF + r0 + cA + 16);
                al[mi][3] = *(const uint32_t*)(smem + AL_OFF + r1 + cA + 16);
            }
#pragma unroll
            for (int nj = 0; nj < 4; nj++) {
                int r = (warpN + nj * 8 + gid) * (PAD * 2);
                int cB = (kb + tig * 2) * 2;
                bh[nj][0] = *(const uint32_t*)(smem + BH_OFF + r + cB);
                bh[nj][1] = *(const uint32_t*)(smem + BH_OFF + r + cB + 16);
                bl[nj][0] = *(const uint32_t*)(smem + BL_OFF + r + cB);
                bl[nj][1] = *(const uint32_t*)(smem + BL_OFF + r + cB + 16);
            }
#pragma unroll
            for (int mi = 0; mi < 4; mi++)
#pragma unroll
                for (int nj = 0; nj < 4; nj++) {
                    mma_bf16(acc[mi][nj], ah[mi], bh[nj]);
                    mma_bf16(acc[mi][nj], ah[mi], bl[nj]);
                    mma_bf16(acc[mi][nj], al[mi], bh[nj]);
                }
        }
    }

    // epilogue: fp16 only
#pragma unroll
    for (int mi = 0; mi < 4; mi++) {
        int r0 = m0 + warpM + mi * 16 + gid;
        int r1 = r0 + 8;
#pragma unroll
        for (int nj = 0; nj < 4; nj++) {
            int c = n0 + warpN + nj * 8 + tig * 2;
            if (r0 < n)
                *(__half2*)&g_h16[(size_t)r0 * F + c] =
                    __floats2half2_rn(acc[mi][nj][0], acc[mi][nj][1]);
            if (r1 < n)
                *(__half2*)&g_h16[(size_t)r1 * F + c] =
                    __floats2half2_rn(acc[mi][nj][2], acc[mi][nj][3]);
        }
    }
}

// ------------------------------------------------------------------
// CSR build
// ------------------------------------------------------------------
__global__ void zero_kernel(int n) {
    int i = blockIdx.x * blockDim.x + threadIdx.x;
    for (; i < n; i += gridDim.x * blockDim.x) {
        g_deg[i] = 0;
        g_fill[i] = 0;
        if (i < 2) g_stats[i] = 0.0;
    }
}

__global__ void deg_kernel(const void* __restrict__ ei, int E, int n) {
    int is64 = probe_is64(ei, E);
    int e = blockIdx.x * blockDim.x + threadIdx.x;
    for (; e < E; e += gridDim.x * blockDim.x) {
        int d = load_idx(ei, (size_t)E + e, is64);
        if ((unsigned)d < (unsigned)n) atomicAdd(&g_deg[d], 1);
    }
}

// scan1 + fused dinv
__global__ void scan1_kernel(int n) {
    int i = blockIdx.x * 512 + threadIdx.x;
    int v = (i < n) ? g_deg[i] : 0;
    if (i < n) g_dinv[i] = rsqrtf((float)(v + 1));
    for (int o = 16; o > 0; o >>= 1) v += __shfl_down_sync(~0u, v, o);
    __shared__ int wsum[16];
    int lane = threadIdx.x & 31, wid = threadIdx.x >> 5;
    if (lane == 0) wsum[wid] = v;
    __syncthreads();
    if (wid == 0) {
        int s = (lane < 16) ? wsum[lane] : 0;
        for (int o = 8; o > 0; o >>= 1) s += __shfl_down_sync(~0u, s, o);
        if (lane == 0) g_partial[blockIdx.x] = s;
    }
}

__global__ void scan2_kernel(int nb) {
    if (threadIdx.x == 0 && blockIdx.x == 0) {
        int acc = 0;
        for (int i = 0; i < nb; i++) { int v = g_partial[i]; g_partial[i] = acc; acc += v; }
    }
}

__global__ void scan3_kernel(int n) {
    int i = blockIdx.x * 512 + threadIdx.x;
    int v = (i < n) ? g_deg[i] : 0;
    int lane = threadIdx.x & 31, wid = threadIdx.x >> 5;
    int s = v;
    for (int o = 1; o < 32; o <<= 1) {
        int t = __shfl_up_sync(~0u, s, o);
        if (lane >= o) s += t;
    }
    __shared__ int wsum[16];
    if (lane == 31) wsum[wid] = s;
    __syncthreads();
    if (wid == 0) {
        int ws = (lane < 16) ? wsum[lane] : 0;
        for (int o = 1; o < 16; o <<= 1) {
            int t = __shfl_up_sync(~0u, ws, o);
            if (lane >= o) ws += t;
        }
        if (lane < 16) wsum[lane] = ws;
    }
    __syncthreads();
    int excl = s - v + (wid > 0 ? wsum[wid - 1] : 0) + g_partial[blockIdx.x];
    if (i < n)  g_ptr[i] = excl;
    if (i == n - 1) g_ptr[n] = excl + v;
}

__global__ void fill_kernel(const void* __restrict__ ei, int E, int n) {
    int is64 = probe_is64(ei, E);
    int e = blockIdx.x * blockDim.x + threadIdx.x;
    for (; e < E; e += gridDim.x * blockDim.x) {
        int s = load_idx(ei, (size_t)e, is64);
        int d = load_idx(ei, (size_t)E + e, is64);
        if ((unsigned)s >= (unsigned)n || (unsigned)d >= (unsigned)n) continue;
        int pos = g_ptr[d] + atomicAdd(&g_fill[d], 1);
        g_csrc[pos] = s;
    }
}

// ------------------------------------------------------------------
// aggregation: warp per node, all-fp16 gathers, unroll x4, fp32 accum
// ------------------------------------------------------------------
__device__ __forceinline__ void acc_row(float* acc, const uint4& p, float nm) {
    const __half2* q = (const __half2*)&p;
#pragma unroll
    for (int j = 0; j < 4; j++) {
        float2 f = __half22float2(q[j]);
        acc[j * 2]     += f.x * nm;
        acc[j * 2 + 1] += f.y * nm;
    }
}

__global__ __launch_bounds__(256) void aggregate_kernel(
    const float* __restrict__ bias, float* __restrict__ out, int n) {
    int wrp = threadIdx.x >> 5;
    int lane = threadIdx.x & 31;
    int node = blockIdx.x * 8 + wrp;
    bool valid = (node < n);

    float acc[8];
#pragma unroll
    for (int q = 0; q < 8; q++) acc[q] = 0.f;

    if (valid) {
        float di = g_dinv[node];
        float w = di * di;
        {
            uint4 ps = *(const uint4*)&g_h16[(size_t)node * F + lane * 8];
            acc_row(acc, ps, w);
        }
        int beg = g_ptr[node], end = g_ptr[node + 1];
        int e = beg;
        for (; e + 3 < end; e += 4) {
            int s0 = g_csrc[e],     s1 = g_csrc[e + 1];
            int s2 = g_csrc[e + 2], s3 = g_csrc[e + 3];
            float nm0 = g_dinv[s0] * di, nm1 = g_dinv[s1] * di;
            float nm2 = g_dinv[s2] * di, nm3 = g_dinv[s3] * di;
            uint4 p0 = *(const uint4*)&g_h16[(size_t)s0 * F + lane * 8];
            uint4 p1 = *(const uint4*)&g_h16[(size_t)s1 * F + lane * 8];
            uint4 p2 = *(const uint4*)&g_h16[(size_t)s2 * F + lane * 8];
            uint4 p3 = *(const uint4*)&g_h16[(size_t)s3 * F + lane * 8];
            acc_row(acc, p0, nm0);
            acc_row(acc, p1, nm1);
            acc_row(acc, p2, nm2);
            acc_row(acc, p3, nm3);
        }
        for (; e < end; e++) {
            int s0 = g_csrc[e];
            float nm0 = g_dinv[s0] * di;
            uint4 p0 = *(const uint4*)&g_h16[(size_t)s0 * F + lane * 8];
            acc_row(acc, p0, nm0);
        }
        const float4* bb = (const float4*)&bias[lane * 8];
        float4 b0 = bb[0], b1 = bb[1];
        acc[0] += b0.x; acc[1] += b0.y; acc[2] += b0.z; acc[3] += b0.w;
        acc[4] += b1.x; acc[5] += b1.y; acc[6] += b1.z; acc[7] += b1.w;
        float4* orow = (float4*)&out[(size_t)node * F + lane * 8];
        orow[0] = make_float4(acc[0], acc[1], acc[2], acc[3]);
        orow[1] = make_float4(acc[4], acc[5], acc[6], acc[7]);
    }

    // fused LN statistics
    float s = 0.f, s2 = 0.f;
#pragma unroll
    for (int q = 0; q < 8; q++) { s += acc[q]; s2 += acc[q] * acc[q]; }
    for (int o = 16; o > 0; o >>= 1) {
        s  += __shfl_down_sync(~0u, s, o);
        s2 += __shfl_down_sync(~0u, s2, o);
    }
    __shared__ float sh_s[8], sh_s2[8];
    if (lane == 0) { sh_s[wrp] = s; sh_s2[wrp] = s2; }
    __syncthreads();
    if (threadIdx.x == 0) {
        double a = 0.0, b = 0.0;
        for (int i = 0; i < 8; i++) { a += (double)sh_s[i]; b += (double)sh_s2[i]; }
        atomicAdd(&g_stats[0], a);
        atomicAdd(&g_stats[1], b);
    }
}

// ------------------------------------------------------------------
// finalize: layernorm + PReLU, float4 vectorized, in place
// ------------------------------------------------------------------
__global__ void finalize_kernel(float* __restrict__ out,
                                const float* __restrict__ lnw,
                                const float* __restrict__ lnb,
                                const float* __restrict__ pa, int M4) {
    int M = M4 * 4;
    double mu = g_stats[0] / (double)M;
    double var = g_stats[1] / (double)M - mu * mu;
    if (var < 0.0) var = 0.0;
    float inv = 1.f / ((float)sqrt(var) + EPS);
    float fmu = (float)mu;
    float alpha = pa[0];
    float4* o4 = (float4*)out;
    int i = blockIdx.x * blockDim.x + threadIdx.x;
    for (; i < M4; i += gridDim.x * blockDim.x) {
        int c = (i * 4) & (F - 1);
        float4 v = o4[i];
        float4 wv = *(const float4*)&lnw[c];
        float4 bv = *(const float4*)&lnb[c];
        float y0 = (v.x - fmu) * inv * wv.x + bv.x;
        float y1 = (v.y - fmu) * inv * wv.y + bv.y;
        float y2 = (v.z - fmu) * inv * wv.z + bv.z;
        float y3 = (v.w - fmu) * inv * wv.w + bv.w;
        o4[i] = make_float4(y0 >= 0.f ? y0 : alpha * y0,
                            y1 >= 0.f ? y1 : alpha * y1,
                            y2 >= 0.f ? y2 : alpha * y2,
                            y3 >= 0.f ? y3 : alpha * y3);
    }
}

// ------------------------------------------------------------------
extern "C" void kernel_launch(void* const* d_in, const int* in_sizes, int n_in,
                              void* d_out, int out_size) {
    const float* x        = (const float*)d_in[0];
    const void*  ei       = d_in[1];
    const float* W        = (const float*)d_in[3];
    const float* conv_b   = (const float*)d_in[4];
    const float* lnw      = (const float*)d_in[5];
    const float* lnb      = (const float*)d_in[6];
    const float* pa       = (const float*)d_in[7];
    float* out = (float*)d_out;

    int n = in_sizes[0] / F;
    int E = in_sizes[1] / 2;
    int M = n * F;
    int nb = (n + 511) / 512;

    cudaFuncSetAttribute(gemm_mma_kernel,
                         cudaFuncAttributeMaxDynamicSharedMemorySize, GSM_TOTAL);

    // side stream + fork/join events (never destroyed; only 2 non-replayed calls)
    cudaStream_t s1;
    cudaStreamCreateWithFlags(&s1, cudaStreamNonBlocking);
    cudaEvent_t eFork, eJoin;
    cudaEventCreateWithFlags(&eFork, cudaEventDisableTiming);
    cudaEventCreateWithFlags(&eJoin, cudaEventDisableTiming);

    // fork: entire CSR branch (incl. zeroing) on s1
    cudaEventRecord(eFork, 0);
    cudaStreamWaitEvent(s1, eFork, 0);
    zero_kernel<<<128, 512, 0, s1>>>(n);
    deg_kernel<<<1024, 256, 0, s1>>>(ei, E, n);
    scan1_kernel<<<nb, 512, 0, s1>>>(n);
    scan2_kernel<<<1, 32, 0, s1>>>(nb);
    scan3_kernel<<<nb, 512, 0, s1>>>(n);
    fill_kernel<<<1024, 256, 0, s1>>>(ei, E, n);
    cudaEventRecord(eJoin, s1);

    // GEMM branch on main stream (starts immediately, concurrent with CSR)
    split_x_kernel<<<1024, 256>>>(x, M / 8);
    split_w_kernel<<<F, F>>>(W);
    gemm_mma_kernel<<<dim3(2, (n + 127) / 128), 256, GSM_TOTAL>>>(n);

    // join, then aggregate + finalize
    cudaStreamWaitEvent(0, eJoin, 0);
    aggregate_kernel<<<(n + 7) / 8, 256>>>(conv_b, out, n);
    finalize_kernel<<<512, 256>>>(out, lnw, lnb, pa, M / 4);
}